// round 1
// baseline (speedup 1.0000x reference)
#include <cuda_runtime.h>
#include <math.h>

// Problem constants
#define HID   1024
#define LT    256
#define LI    2048
#define LTOT  2304
#define NHEAD 16
#define HD    64
#define MLPD  4096

// ---------------- scratch (device globals; no cudaMalloc allowed) ----------
__device__ float g_mod[12288];
__device__ float g_imgm[LI * HID];
__device__ float g_txtm[LT * HID];
__device__ float g_qkv_img[LI * 3 * HID];
__device__ float g_qkv_txt[LT * 3 * HID];
__device__ float g_q[NHEAD * LTOT * HD];
__device__ float g_k[NHEAD * LTOT * HD];
__device__ float g_v[NHEAD * LTOT * HD];
__device__ float g_attn[LTOT * HID];
__device__ float g_img2[LI * HID];
__device__ float g_ln2[LI * HID];
__device__ float g_mlp[LI * MLPD];

// ---------------- modulation: silu(vec) @ mod_w + mod_b --------------------
// 96 blocks x 128 threads. Blocks 0..47 -> img mod cols, 48..95 -> txt.
__global__ void mod_kernel(const float* __restrict__ vec,
                           const float* __restrict__ imw, const float* __restrict__ imb,
                           const float* __restrict__ tmw, const float* __restrict__ tmb,
                           float* __restrict__ mod)
{
    __shared__ float sv[HID];
    int tid = threadIdx.x;
    for (int i = tid; i < HID; i += 128) {
        float x = vec[i];
        sv[i] = x / (1.f + expf(-x));
    }
    __syncthreads();
    int blk = blockIdx.x;
    bool is_img = blk < 48;
    int col = (is_img ? blk : blk - 48) * 128 + tid;
    const float* w = is_img ? imw : tmw;
    const float* b = is_img ? imb : tmb;
    float* out = mod + (is_img ? 0 : 6144);
    float a0 = 0.f, a1 = 0.f, a2 = 0.f, a3 = 0.f;
    for (int d = 0; d < HID; d += 4) {
        a0 += sv[d + 0] * w[(d + 0) * 6144 + col];
        a1 += sv[d + 1] * w[(d + 1) * 6144 + col];
        a2 += sv[d + 2] * w[(d + 2) * 6144 + col];
        a3 += sv[d + 3] * w[(d + 3) * 6144 + col];
    }
    out[col] = b[col] + ((a0 + a1) + (a2 + a3));
}

// ---------------- fused LayerNorm + modulate -------------------------------
// one block (256 threads) per row of 1024. out = (1+scale)*ln(x) + shift
__global__ void ln_mod_kernel(const float* __restrict__ x,
                              const float* __restrict__ mod,
                              int shift_off, int scale_off,
                              float* __restrict__ out)
{
    __shared__ float red[2][8];
    int row = blockIdx.x, tid = threadIdx.x;
    float4 xv = ((const float4*)(x + row * HID))[tid];
    float s  = xv.x + xv.y + xv.z + xv.w;
    float s2 = xv.x * xv.x + xv.y * xv.y + xv.z * xv.z + xv.w * xv.w;
    #pragma unroll
    for (int o = 16; o; o >>= 1) {
        s  += __shfl_xor_sync(0xffffffffu, s,  o);
        s2 += __shfl_xor_sync(0xffffffffu, s2, o);
    }
    int warp = tid >> 5, lane = tid & 31;
    if (lane == 0) { red[0][warp] = s; red[1][warp] = s2; }
    __syncthreads();
    s = 0.f; s2 = 0.f;
    #pragma unroll
    for (int w = 0; w < 8; w++) { s += red[0][w]; s2 += red[1][w]; }
    float mean = s * (1.f / HID);
    float var  = s2 * (1.f / HID) - mean * mean;
    float rs = rsqrtf(var + 1e-6f);
    int c = tid * 4;
    float4 sc = *(const float4*)(mod + scale_off + c);
    float4 sh = *(const float4*)(mod + shift_off + c);
    float4 o;
    o.x = (xv.x - mean) * rs * (1.f + sc.x) + sh.x;
    o.y = (xv.y - mean) * rs * (1.f + sc.y) + sh.y;
    o.z = (xv.z - mean) * rs * (1.f + sc.z) + sh.z;
    o.w = (xv.w - mean) * rs * (1.f + sc.w) + sh.w;
    ((float4*)(out + row * HID))[tid] = o;
}

// ---------------- SGEMM 128x128x8, 256 threads, 8x8 per thread -------------
// EPI: 0 = +bias ; 1 = gelu(+bias) ; 2 = res + gate[col]*(+bias)
__device__ __forceinline__ float gelu_tanh(float x)
{
    return 0.5f * x * (1.f + tanhf(0.7978845608028654f * (x + 0.044715f * x * x * x)));
}

template <int EPI>
__global__ void __launch_bounds__(256) sgemm_k(
    const float* __restrict__ A, const float* __restrict__ Bm,
    const float* __restrict__ bias, const float* __restrict__ res,
    const float* __restrict__ gate, float* __restrict__ C,
    int M, int N, int K)
{
    __shared__ float As[8][128];
    __shared__ float Bs[8][132];
    int tid = threadIdx.x;
    int tx = tid & 15, ty = tid >> 4;
    int row0 = blockIdx.y * 128;
    int col0 = blockIdx.x * 128;

    float acc[8][8];
    #pragma unroll
    for (int i = 0; i < 8; i++)
        #pragma unroll
        for (int j = 0; j < 8; j++) acc[i][j] = 0.f;

    int ar  = tid >> 1;
    int ac4 = (tid & 1) * 4;
    int br  = tid >> 5;
    int bc4 = (tid & 31) * 4;
    const float* Aptr = A + (size_t)(row0 + ar) * K + ac4;
    const float* Bptr = Bm + (size_t)br * N + col0 + bc4;

    for (int k0 = 0; k0 < K; k0 += 8) {
        float4 av = *(const float4*)Aptr; Aptr += 8;
        float4 bv = *(const float4*)Bptr; Bptr += (size_t)8 * N;
        As[ac4 + 0][ar] = av.x; As[ac4 + 1][ar] = av.y;
        As[ac4 + 2][ar] = av.z; As[ac4 + 3][ar] = av.w;
        *(float4*)&Bs[br][bc4] = bv;
        __syncthreads();
        #pragma unroll
        for (int kk = 0; kk < 8; kk++) {
            float4 a0 = *(const float4*)&As[kk][ty * 8];
            float4 a1 = *(const float4*)&As[kk][ty * 8 + 4];
            float4 b0 = *(const float4*)&Bs[kk][tx * 8];
            float4 b1 = *(const float4*)&Bs[kk][tx * 8 + 4];
            float a[8] = {a0.x, a0.y, a0.z, a0.w, a1.x, a1.y, a1.z, a1.w};
            float b[8] = {b0.x, b0.y, b0.z, b0.w, b1.x, b1.y, b1.z, b1.w};
            #pragma unroll
            for (int i = 0; i < 8; i++)
                #pragma unroll
                for (int j = 0; j < 8; j++) acc[i][j] += a[i] * b[j];
        }
        __syncthreads();
    }

    #pragma unroll
    for (int i = 0; i < 8; i++) {
        int r = row0 + ty * 8 + i;
        #pragma unroll
        for (int jj = 0; jj < 8; jj += 4) {
            int c = col0 + tx * 8 + jj;
            float4 bv = *(const float4*)(bias + c);
            float4 v;
            v.x = acc[i][jj + 0] + bv.x;
            v.y = acc[i][jj + 1] + bv.y;
            v.z = acc[i][jj + 2] + bv.z;
            v.w = acc[i][jj + 3] + bv.w;
            if (EPI == 1) {
                v.x = gelu_tanh(v.x); v.y = gelu_tanh(v.y);
                v.z = gelu_tanh(v.z); v.w = gelu_tanh(v.w);
            } else if (EPI == 2) {
                float4 rr = *(const float4*)(res + (size_t)r * N + c);
                float4 gg = *(const float4*)(gate + c);
                v.x = rr.x + gg.x * v.x;
                v.y = rr.y + gg.y * v.y;
                v.z = rr.z + gg.z * v.z;
                v.w = rr.w + gg.w * v.w;
            }
            *(float4*)&C[(size_t)r * N + c] = v;
        }
    }
}

// ---------------- build q/k/v: rms-norm + rope + head layout ---------------
// one block per sequence position s (0..2303); 8 warps, 48 (head,which) units
__global__ void build_qkv_kernel(const float* __restrict__ qkv_img,
                                 const float* __restrict__ qkv_txt,
                                 const float* __restrict__ iqs, const float* __restrict__ iks,
                                 const float* __restrict__ tqs, const float* __restrict__ tks,
                                 const float* __restrict__ pe,
                                 float* __restrict__ q, float* __restrict__ k,
                                 float* __restrict__ v)
{
    int s = blockIdx.x;
    int warp = threadIdx.x >> 5, lane = threadIdx.x & 31;
    bool is_txt = s < LT;
    const float* src = is_txt ? (qkv_txt + (size_t)s * 3072)
                              : (qkv_img + (size_t)(s - LT) * 3072);
    for (int u = warp; u < 48; u += 8) {
        int which = u >> 4;       // 0=q 1=k 2=v
        int h = u & 15;
        const float* base = src + which * HID + h * HD;
        float x0 = base[2 * lane], x1 = base[2 * lane + 1];
        size_t didx = ((size_t)h * LTOT + s) * HD + 2 * lane;
        if (which == 2) {
            v[didx] = x0; v[didx + 1] = x1;
        } else {
            float ss = x0 * x0 + x1 * x1;
            #pragma unroll
            for (int o = 16; o; o >>= 1) ss += __shfl_xor_sync(0xffffffffu, ss, o);
            float r = rsqrtf(ss * (1.f / HD) + 1e-6f);
            const float* sc = (which == 0) ? (is_txt ? tqs : iqs)
                                           : (is_txt ? tks : iks);
            x0 *= r * sc[2 * lane];
            x1 *= r * sc[2 * lane + 1];
            const float* p = pe + (size_t)s * 128 + lane * 4;
            float o0 = p[0] * x0 + p[1] * x1;
            float o1 = p[2] * x0 + p[3] * x1;
            if (which == 0) { o0 *= 0.125f; o1 *= 0.125f; }  // fold 1/sqrt(HD)
            float* dst = (which == 0) ? q : k;
            dst[didx] = o0; dst[didx + 1] = o1;
        }
    }
}

// ---------------- flash attention: BQ=BK=64, HD=64, fp32 -------------------
// grid (36 q-tiles, 16 heads), 256 threads (tx 0..15 -> 4 cols, ty 0..15 -> 4 rows)
#define FA_PAD 68
__global__ void __launch_bounds__(256) flash_kernel(
    const float* __restrict__ Q, const float* __restrict__ Kg,
    const float* __restrict__ Vg, float* __restrict__ O)
{
    extern __shared__ float sm[];
    float* Qst = sm;                 // [d][q]  (d-major, 68 stride)
    float* Kst = sm + 64 * FA_PAD;   // [d][k]
    float* Vs  = sm + 2 * 64 * FA_PAD;  // [k][d]
    float* Pst = sm + 3 * 64 * FA_PAD;  // [k][q]

    int tid = threadIdx.x;
    int tx = tid & 15, ty = tid >> 4;
    int h = blockIdx.y;
    int qb = blockIdx.x * 64;
    const float* Qh = Q + ((size_t)h * LTOT + qb) * HD;
    const float* Kh = Kg + (size_t)h * LTOT * HD;
    const float* Vh = Vg + (size_t)h * LTOT * HD;

    #pragma unroll
    for (int l = 0; l < 4; l++) {
        int f = tid + l * 256;
        int row = f >> 4, c4 = (f & 15) * 4;
        float4 v = *(const float4*)(Qh + row * HD + c4);
        Qst[(c4 + 0) * FA_PAD + row] = v.x;
        Qst[(c4 + 1) * FA_PAD + row] = v.y;
        Qst[(c4 + 2) * FA_PAD + row] = v.z;
        Qst[(c4 + 3) * FA_PAD + row] = v.w;
    }

    float m0[4], l0[4], acc[4][4];
    #pragma unroll
    for (int i = 0; i < 4; i++) {
        m0[i] = -1e30f; l0[i] = 0.f;
        acc[i][0] = acc[i][1] = acc[i][2] = acc[i][3] = 0.f;
    }

    for (int kb = 0; kb < LTOT; kb += 64) {
        #pragma unroll
        for (int l = 0; l < 4; l++) {
            int f = tid + l * 256;
            int row = f >> 4, c4 = (f & 15) * 4;
            float4 kv = *(const float4*)(Kh + (size_t)(kb + row) * HD + c4);
            Kst[(c4 + 0) * FA_PAD + row] = kv.x;
            Kst[(c4 + 1) * FA_PAD + row] = kv.y;
            Kst[(c4 + 2) * FA_PAD + row] = kv.z;
            Kst[(c4 + 3) * FA_PAD + row] = kv.w;
            float4 vv = *(const float4*)(Vh + (size_t)(kb + row) * HD + c4);
            *(float4*)&Vs[row * FA_PAD + c4] = vv;
        }
        __syncthreads();

        float s[4][4];
        #pragma unroll
        for (int i = 0; i < 4; i++) s[i][0] = s[i][1] = s[i][2] = s[i][3] = 0.f;
        #pragma unroll 8
        for (int d = 0; d < 64; d++) {
            float4 qv = *(const float4*)&Qst[d * FA_PAD + ty * 4];
            float4 kv = *(const float4*)&Kst[d * FA_PAD + tx * 4];
            float qa[4] = {qv.x, qv.y, qv.z, qv.w};
            float ka[4] = {kv.x, kv.y, kv.z, kv.w};
            #pragma unroll
            for (int i = 0; i < 4; i++)
                #pragma unroll
                for (int j = 0; j < 4; j++) s[i][j] += qa[i] * ka[j];
        }

        #pragma unroll
        for (int i = 0; i < 4; i++) {
            float tm = fmaxf(fmaxf(s[i][0], s[i][1]), fmaxf(s[i][2], s[i][3]));
            #pragma unroll
            for (int o = 8; o; o >>= 1) tm = fmaxf(tm, __shfl_xor_sync(0xffffffffu, tm, o));
            float mn = fmaxf(m0[i], tm);
            float corr = __expf(m0[i] - mn);
            float ps = 0.f;
            #pragma unroll
            for (int j = 0; j < 4; j++) {
                float p = __expf(s[i][j] - mn);
                ps += p;
                Pst[(tx * 4 + j) * FA_PAD + ty * 4 + i] = p;
            }
            #pragma unroll
            for (int o = 8; o; o >>= 1) ps += __shfl_xor_sync(0xffffffffu, ps, o);
            l0[i] = l0[i] * corr + ps;
            m0[i] = mn;
            acc[i][0] *= corr; acc[i][1] *= corr;
            acc[i][2] *= corr; acc[i][3] *= corr;
        }
        __syncthreads();

        #pragma unroll 8
        for (int kk = 0; kk < 64; kk++) {
            float4 pv = *(const float4*)&Pst[kk * FA_PAD + ty * 4];
            float4 vv = *(const float4*)&Vs[kk * FA_PAD + tx * 4];
            float pa[4] = {pv.x, pv.y, pv.z, pv.w};
            float va[4] = {vv.x, vv.y, vv.z, vv.w};
            #pragma unroll
            for (int i = 0; i < 4; i++)
                #pragma unroll
                for (int j = 0; j < 4; j++) acc[i][j] += pa[i] * va[j];
        }
        __syncthreads();
    }

    #pragma unroll
    for (int i = 0; i < 4; i++) {
        float inv = 1.f / l0[i];
        int srow = qb + ty * 4 + i;
        float4 o = {acc[i][0] * inv, acc[i][1] * inv, acc[i][2] * inv, acc[i][3] * inv};
        *(float4*)&O[(size_t)srow * HID + h * HD + tx * 4] = o;
    }
}

// ---------------- launch ---------------------------------------------------
extern "C" void kernel_launch(void* const* d_in, const int* in_sizes, int n_in,
                              void* d_out, int out_size)
{
    const float* img   = (const float*)d_in[0];
    const float* txt   = (const float*)d_in[1];
    const float* pe    = (const float*)d_in[2];
    const float* vec   = (const float*)d_in[3];
    const float* imw   = (const float*)d_in[4];
    const float* imb   = (const float*)d_in[5];
    const float* tmw   = (const float*)d_in[6];
    const float* tmb   = (const float*)d_in[7];
    const float* iqkvw = (const float*)d_in[8];
    const float* iqkvb = (const float*)d_in[9];
    const float* iqs   = (const float*)d_in[10];
    const float* iks   = (const float*)d_in[11];
    const float* projw = (const float*)d_in[12];
    const float* projb = (const float*)d_in[13];
    const float* tqkvw = (const float*)d_in[14];
    const float* tqkvb = (const float*)d_in[15];
    const float* tqs   = (const float*)d_in[16];
    const float* tks   = (const float*)d_in[17];
    const float* w1    = (const float*)d_in[18];
    const float* b1    = (const float*)d_in[19];
    const float* w2    = (const float*)d_in[20];
    const float* b2    = (const float*)d_in[21];

    float *mod, *imgm, *txtm, *qi, *qt, *q, *k, *v, *attn, *img2, *ln2, *mlp;
    cudaGetSymbolAddress((void**)&mod,  g_mod);
    cudaGetSymbolAddress((void**)&imgm, g_imgm);
    cudaGetSymbolAddress((void**)&txtm, g_txtm);
    cudaGetSymbolAddress((void**)&qi,   g_qkv_img);
    cudaGetSymbolAddress((void**)&qt,   g_qkv_txt);
    cudaGetSymbolAddress((void**)&q,    g_q);
    cudaGetSymbolAddress((void**)&k,    g_k);
    cudaGetSymbolAddress((void**)&v,    g_v);
    cudaGetSymbolAddress((void**)&attn, g_attn);
    cudaGetSymbolAddress((void**)&img2, g_img2);
    cudaGetSymbolAddress((void**)&ln2,  g_ln2);
    cudaGetSymbolAddress((void**)&mlp,  g_mlp);

    cudaFuncSetAttribute(flash_kernel, cudaFuncAttributeMaxDynamicSharedMemorySize,
                         4 * 64 * FA_PAD * 4);

    // 1) modulation vectors
    mod_kernel<<<96, 128>>>(vec, imw, imb, tmw, tmb, mod);
    // 2) LN + modulate (img, txt)
    ln_mod_kernel<<<LI, 256>>>(img, mod, 0, 1024, imgm);
    ln_mod_kernel<<<LT, 256>>>(txt, mod, 6144, 7168, txtm);
    // 3) QKV GEMMs
    { dim3 g(24, 16); sgemm_k<0><<<g, 256>>>(imgm, iqkvw, iqkvb, nullptr, nullptr, qi, LI, 3072, HID); }
    { dim3 g(24, 2);  sgemm_k<0><<<g, 256>>>(txtm, tqkvw, tqkvb, nullptr, nullptr, qt, LT, 3072, HID); }
    // 4) rms-norm + rope + head layout (attn scale folded into q)
    build_qkv_kernel<<<LTOT, 256>>>(qi, qt, iqs, iks, tqs, tks, pe, q, k, v);
    // 5) attention
    { dim3 g(LTOT / 64, NHEAD);
      flash_kernel<<<g, 256, 4 * 64 * FA_PAD * 4>>>(q, k, v, attn); }
    // 6) proj + gated residual (img rows only: skip first 256 rows of attn)
    { dim3 g(8, 16); sgemm_k<2><<<g, 256>>>(attn + (size_t)LT * HID, projw, projb,
                                            img, mod + 2048, img2, LI, HID, HID); }
    // 7) LN2 + modulate
    ln_mod_kernel<<<LI, 256>>>(img2, mod, 3072, 4096, ln2);
    // 8) MLP
    { dim3 g(32, 16); sgemm_k<1><<<g, 256>>>(ln2, w1, b1, nullptr, nullptr, mlp, LI, MLPD, HID); }
    { dim3 g(8, 16);  sgemm_k<2><<<g, 256>>>(mlp, w2, b2, img2, mod + 5120,
                                             (float*)d_out, LI, HID, MLPD); }
}

// round 3
// speedup vs baseline: 2.1238x; 2.1238x over previous
#include <cuda_runtime.h>
#include <cstdint>
#include <math.h>

// Problem constants
#define HID   1024
#define LT    256
#define LI    2048
#define LTOT  2304
#define NHEAD 16
#define HD    64
#define MLPD  4096

// ---------------- scratch (device globals; no cudaMalloc allowed) ----------
__device__ float g_mod[12288];
__device__ float g_imgm[LI * HID];
__device__ float g_txtm[LT * HID];
__device__ float g_qkv_img[LI * 3 * HID];
__device__ float g_qkv_txt[LT * 3 * HID];
__device__ float g_q[NHEAD * LTOT * HD];
__device__ float g_k[NHEAD * LTOT * HD];
__device__ float g_v[NHEAD * LTOT * HD];
__device__ float g_attn[LTOT * HID];
__device__ float g_img2[LI * HID];
__device__ float g_ln2[LI * HID];
__device__ float g_mlp[LI * MLPD];
// transposed weights [N,K]
__device__ float g_wt_iqkv[3 * HID * HID];
__device__ float g_wt_tqkv[3 * HID * HID];
__device__ float g_wt_proj[HID * HID];
__device__ float g_wt_w1[MLPD * HID];
__device__ float g_wt_w2[HID * MLPD];

// ---------------- PTX helpers ----------------------------------------------
__device__ __forceinline__ uint32_t smem_u32(const void* p) {
    uint32_t a;
    asm("{ .reg .u64 t; cvta.to.shared.u64 t, %1; cvt.u32.u64 %0, t; }" : "=r"(a) : "l"(p));
    return a;
}
#define CP_ASYNC16(dst, src) \
    asm volatile("cp.async.cg.shared.global [%0], [%1], 16;" :: "r"(dst), "l"(src))
#define CP_COMMIT() asm volatile("cp.async.commit_group;")
#define CP_WAIT(n)  asm volatile("cp.async.wait_group %0;" :: "n"(n))

#define LDSM_X4(r, a)                                                          \
    asm volatile("ldmatrix.sync.aligned.m8n8.x4.shared.b16 {%0,%1,%2,%3}, [%4];" \
        : "=r"((r)[0]), "=r"((r)[1]), "=r"((r)[2]), "=r"((r)[3]) : "r"(a))

#define CVT_TF32(x) asm volatile("cvt.rna.tf32.f32 %0, %0;" : "+r"(x))

#define MMA_TF32(d, a, b0, b1)                                                 \
    asm volatile("mma.sync.aligned.m16n8k8.row.col.f32.tf32.tf32.f32 "         \
        "{%0,%1,%2,%3}, {%4,%5,%6,%7}, {%8,%9}, {%0,%1,%2,%3};"                \
        : "+f"((d)[0]), "+f"((d)[1]), "+f"((d)[2]), "+f"((d)[3])               \
        : "r"((a)[0]), "r"((a)[1]), "r"((a)[2]), "r"((a)[3]),                  \
          "r"(b0), "r"(b1))

// ---------------- weight transpose: W[K,N] -> WT[N,K] ----------------------
__global__ void transpose_k(const float* __restrict__ W, float* __restrict__ WT,
                            int K, int N)
{
    __shared__ float t[32][33];
    int n0 = blockIdx.x * 32, k0 = blockIdx.y * 32;
    int tx = threadIdx.x, ty = threadIdx.y;
    #pragma unroll
    for (int i = 0; i < 32; i += 8)
        t[ty + i][tx] = W[(size_t)(k0 + ty + i) * N + n0 + tx];
    __syncthreads();
    #pragma unroll
    for (int i = 0; i < 32; i += 8)
        WT[(size_t)(n0 + ty + i) * K + k0 + tx] = t[tx][ty + i];
}

// ---------------- modulation: silu(vec) @ mod_w + mod_b --------------------
__global__ void mod_kernel(const float* __restrict__ vec,
                           const float* __restrict__ imw, const float* __restrict__ imb,
                           const float* __restrict__ tmw, const float* __restrict__ tmb,
                           float* __restrict__ mod)
{
    __shared__ float sv[HID];
    int tid = threadIdx.x;
    for (int i = tid; i < HID; i += 128) {
        float x = vec[i];
        sv[i] = x / (1.f + expf(-x));
    }
    __syncthreads();
    int blk = blockIdx.x;
    bool is_img = blk < 48;
    int col = (is_img ? blk : blk - 48) * 128 + tid;
    const float* w = is_img ? imw : tmw;
    const float* b = is_img ? imb : tmb;
    float* out = mod + (is_img ? 0 : 6144);
    float a0 = 0.f, a1 = 0.f, a2 = 0.f, a3 = 0.f;
    for (int d = 0; d < HID; d += 4) {
        a0 += sv[d + 0] * w[(d + 0) * 6144 + col];
        a1 += sv[d + 1] * w[(d + 1) * 6144 + col];
        a2 += sv[d + 2] * w[(d + 2) * 6144 + col];
        a3 += sv[d + 3] * w[(d + 3) * 6144 + col];
    }
    out[col] = b[col] + ((a0 + a1) + (a2 + a3));
}

// ---------------- fused LayerNorm + modulate -------------------------------
__global__ void ln_mod_kernel(const float* __restrict__ x,
                              const float* __restrict__ mod,
                              int shift_off, int scale_off,
                              float* __restrict__ out)
{
    __shared__ float red[2][8];
    int row = blockIdx.x, tid = threadIdx.x;
    float4 xv = ((const float4*)(x + row * HID))[tid];
    float s  = xv.x + xv.y + xv.z + xv.w;
    float s2 = xv.x * xv.x + xv.y * xv.y + xv.z * xv.z + xv.w * xv.w;
    #pragma unroll
    for (int o = 16; o; o >>= 1) {
        s  += __shfl_xor_sync(0xffffffffu, s,  o);
        s2 += __shfl_xor_sync(0xffffffffu, s2, o);
    }
    int warp = tid >> 5, lane = tid & 31;
    if (lane == 0) { red[0][warp] = s; red[1][warp] = s2; }
    __syncthreads();
    s = 0.f; s2 = 0.f;
    #pragma unroll
    for (int w = 0; w < 8; w++) { s += red[0][w]; s2 += red[1][w]; }
    float mean = s * (1.f / HID);
    float var  = s2 * (1.f / HID) - mean * mean;
    float rs = rsqrtf(var + 1e-6f);
    int c = tid * 4;
    float4 sc = *(const float4*)(mod + scale_off + c);
    float4 sh = *(const float4*)(mod + shift_off + c);
    float4 o;
    o.x = (xv.x - mean) * rs * (1.f + sc.x) + sh.x;
    o.y = (xv.y - mean) * rs * (1.f + sc.y) + sh.y;
    o.z = (xv.z - mean) * rs * (1.f + sc.z) + sh.z;
    o.w = (xv.w - mean) * rs * (1.f + sc.w) + sh.w;
    ((float4*)(out + row * HID))[tid] = o;
}

// ---------------- tf32 mma.sync GEMM: C[M,N] = A[M,K] @ BT[N,K]^T ----------
// CTA 128x128, BK=32, double-buffered cp.async, padded smem rows (36 floats).
// 8 warps: warp_m = wid&3 (32 rows), warp_n = wid>>2 (64 cols).
// EPI: 0 = +bias ; 1 = gelu(+bias) ; 2 = res + gate[col]*(+bias)
__device__ __forceinline__ float gelu_tanh(float x)
{
    return 0.5f * x * (1.f + tanhf(0.7978845608028654f * (x + 0.044715f * x * x * x)));
}

#define ROWB 144                       // bytes per padded smem row (32+4 floats)
#define TILEB (128 * ROWB)             // 18432 B per tile
#define MM_SMEM (4 * TILEB)            // A0 A1 B0 B1 = 73728 B

__device__ __forceinline__ void mm_load_tile(uint32_t sbase, const float* __restrict__ g,
                                             int K, int k0)
{
    int tid = threadIdx.x;
    #pragma unroll
    for (int i = 0; i < 4; i++) {
        int id = tid + i * 256;
        int r = id >> 3, c = id & 7;
        uint32_t dst = sbase + r * ROWB + c * 16;
        const float* src = g + (size_t)r * K + k0 + c * 4;
        CP_ASYNC16(dst, src);
    }
}

template <int EPI>
__global__ void __launch_bounds__(256) mma_gemm(
    const float* __restrict__ A, const float* __restrict__ BT,
    const float* __restrict__ bias, const float* __restrict__ res,
    const float* __restrict__ gate, float* __restrict__ C,
    int N, int K)
{
    extern __shared__ char smem[];
    uint32_t su = smem_u32(smem);
    uint32_t sA[2] = { su,              su + TILEB };
    uint32_t sB[2] = { su + 2 * TILEB,  su + 3 * TILEB };

    int tid = threadIdx.x;
    int wid = tid >> 5, lane = tid & 31;
    int warp_m = wid & 3, warp_n = wid >> 2;
    int row0 = blockIdx.y * 128;
    int col0 = blockIdx.x * 128;
    const float* Ab = A + (size_t)row0 * K;
    const float* Bb = BT + (size_t)col0 * K;

    float acc[2][8][4];
    #pragma unroll
    for (int mt = 0; mt < 2; mt++)
        #pragma unroll
        for (int nt = 0; nt < 8; nt++)
            #pragma unroll
            for (int e = 0; e < 4; e++) acc[mt][nt][e] = 0.f;

    // ldmatrix per-lane byte offsets within a tile
    uint32_t aoff = (uint32_t)((warp_m * 32 + (lane & 15)) * ROWB + ((lane >> 4) & 1) * 16);
    uint32_t boff = (uint32_t)((warp_n * 64 + (lane & 7) + ((lane >> 4) & 1) * 8) * ROWB
                               + (lane & 8 ? 16 : 0));

    int T = K >> 5;
    mm_load_tile(sA[0], Ab, K, 0);
    mm_load_tile(sB[0], Bb, K, 0);
    CP_COMMIT();

    for (int t = 0; t < T; t++) {
        int b = t & 1;
        if (t + 1 < T) {
            mm_load_tile(sA[b ^ 1], Ab, K, (t + 1) * 32);
            mm_load_tile(sB[b ^ 1], Bb, K, (t + 1) * 32);
            CP_COMMIT();
            CP_WAIT(1);
        } else {
            CP_WAIT(0);
        }
        __syncthreads();

        uint32_t Abase = sA[b] + aoff;
        uint32_t Bbase = sB[b] + boff;
        #pragma unroll
        for (int ks = 0; ks < 4; ks++) {
            uint32_t af[2][4], bf[4][4];
            LDSM_X4(af[0], Abase + ks * 32);
            LDSM_X4(af[1], Abase + 16 * ROWB + ks * 32);
            #pragma unroll
            for (int p = 0; p < 4; p++)
                LDSM_X4(bf[p], Bbase + p * 16 * ROWB + ks * 32);
            #pragma unroll
            for (int mt = 0; mt < 2; mt++)
                #pragma unroll
                for (int e = 0; e < 4; e++) CVT_TF32(af[mt][e]);
            #pragma unroll
            for (int p = 0; p < 4; p++)
                #pragma unroll
                for (int e = 0; e < 4; e++) CVT_TF32(bf[p][e]);
            #pragma unroll
            for (int mt = 0; mt < 2; mt++)
                #pragma unroll
                for (int nt = 0; nt < 8; nt++) {
                    uint32_t b0 = bf[nt >> 1][(nt & 1) ? 2 : 0];
                    uint32_t b1 = bf[nt >> 1][(nt & 1) ? 3 : 1];
                    MMA_TF32(acc[mt][nt], af[mt], b0, b1);
                }
        }
        __syncthreads();
    }

    // epilogue: c0,c1 -> (row, col..col+1); c2,c3 -> (row+8, col..col+1)
    int qr = lane >> 2, qc = (lane & 3) * 2;
    #pragma unroll
    for (int mt = 0; mt < 2; mt++) {
        int gr0 = row0 + warp_m * 32 + mt * 16 + qr;
        #pragma unroll
        for (int nt = 0; nt < 8; nt++) {
            int gc = col0 + warp_n * 64 + nt * 8 + qc;
            float2 bv = *(const float2*)(bias + gc);
            #pragma unroll
            for (int h = 0; h < 2; h++) {
                int gr = gr0 + h * 8;
                float2 v;
                v.x = acc[mt][nt][2 * h + 0] + bv.x;
                v.y = acc[mt][nt][2 * h + 1] + bv.y;
                if (EPI == 1) {
                    v.x = gelu_tanh(v.x);
                    v.y = gelu_tanh(v.y);
                } else if (EPI == 2) {
                    float2 rr = *(const float2*)(res + (size_t)gr * N + gc);
                    float2 gg = *(const float2*)(gate + gc);
                    v.x = rr.x + gg.x * v.x;
                    v.y = rr.y + gg.y * v.y;
                }
                *(float2*)&C[(size_t)gr * N + gc] = v;
            }
        }
    }
}

// ---------------- build q/k/v: rms-norm + rope + head layout ---------------
__global__ void build_qkv_kernel(const float* __restrict__ qkv_img,
                                 const float* __restrict__ qkv_txt,
                                 const float* __restrict__ iqs, const float* __restrict__ iks,
                                 const float* __restrict__ tqs, const float* __restrict__ tks,
                                 const float* __restrict__ pe,
                                 float* __restrict__ q, float* __restrict__ k,
                                 float* __restrict__ v)
{
    int s = blockIdx.x;
    int warp = threadIdx.x >> 5, lane = threadIdx.x & 31;
    bool is_txt = s < LT;
    const float* src = is_txt ? (qkv_txt + (size_t)s * 3072)
                              : (qkv_img + (size_t)(s - LT) * 3072);
    for (int u = warp; u < 48; u += 8) {
        int which = u >> 4;       // 0=q 1=k 2=v
        int h = u & 15;
        const float* base = src + which * HID + h * HD;
        float x0 = base[2 * lane], x1 = base[2 * lane + 1];
        size_t didx = ((size_t)h * LTOT + s) * HD + 2 * lane;
        if (which == 2) {
            v[didx] = x0; v[didx + 1] = x1;
        } else {
            float ss = x0 * x0 + x1 * x1;
            #pragma unroll
            for (int o = 16; o; o >>= 1) ss += __shfl_xor_sync(0xffffffffu, ss, o);
            float r = rsqrtf(ss * (1.f / HD) + 1e-6f);
            const float* sc = (which == 0) ? (is_txt ? tqs : iqs)
                                           : (is_txt ? tks : iks);
            x0 *= r * sc[2 * lane];
            x1 *= r * sc[2 * lane + 1];
            const float* p = pe + (size_t)s * 128 + lane * 4;
            float o0 = p[0] * x0 + p[1] * x1;
            float o1 = p[2] * x0 + p[3] * x1;
            if (which == 0) { o0 *= 0.125f; o1 *= 0.125f; }  // fold 1/sqrt(HD)
            float* dst = (which == 0) ? q : k;
            dst[didx] = o0; dst[didx + 1] = o1;
        }
    }
}

// ---------------- flash attention: BQ=BK=64, HD=64, fp32 -------------------
#define FA_PAD 68
__global__ void __launch_bounds__(256) flash_kernel(
    const float* __restrict__ Q, const float* __restrict__ Kg,
    const float* __restrict__ Vg, float* __restrict__ O)
{
    extern __shared__ float sm[];
    float* Qst = sm;
    float* Kst = sm + 64 * FA_PAD;
    float* Vs  = sm + 2 * 64 * FA_PAD;
    float* Pst = sm + 3 * 64 * FA_PAD;

    int tid = threadIdx.x;
    int tx = tid & 15, ty = tid >> 4;
    int h = blockIdx.y;
    int qb = blockIdx.x * 64;
    const float* Qh = Q + ((size_t)h * LTOT + qb) * HD;
    const float* Kh = Kg + (size_t)h * LTOT * HD;
    const float* Vh = Vg + (size_t)h * LTOT * HD;

    #pragma unroll
    for (int l = 0; l < 4; l++) {
        int f = tid + l * 256;
        int row = f >> 4, c4 = (f & 15) * 4;
        float4 v = *(const float4*)(Qh + row * HD + c4);
        Qst[(c4 + 0) * FA_PAD + row] = v.x;
        Qst[(c4 + 1) * FA_PAD + row] = v.y;
        Qst[(c4 + 2) * FA_PAD + row] = v.z;
        Qst[(c4 + 3) * FA_PAD + row] = v.w;
    }

    float m0[4], l0[4], acc[4][4];
    #pragma unroll
    for (int i = 0; i < 4; i++) {
        m0[i] = -1e30f; l0[i] = 0.f;
        acc[i][0] = acc[i][1] = acc[i][2] = acc[i][3] = 0.f;
    }

    for (int kb = 0; kb < LTOT; kb += 64) {
        #pragma unroll
        for (int l = 0; l < 4; l++) {
            int f = tid + l * 256;
            int row = f >> 4, c4 = (f & 15) * 4;
            float4 kv = *(const float4*)(Kh + (size_t)(kb + row) * HD + c4);
            Kst[(c4 + 0) * FA_PAD + row] = kv.x;
            Kst[(c4 + 1) * FA_PAD + row] = kv.y;
            Kst[(c4 + 2) * FA_PAD + row] = kv.z;
            Kst[(c4 + 3) * FA_PAD + row] = kv.w;
            float4 vv = *(const float4*)(Vh + (size_t)(kb + row) * HD + c4);
            *(float4*)&Vs[row * FA_PAD + c4] = vv;
        }
        __syncthreads();

        float s[4][4];
        #pragma unroll
        for (int i = 0; i < 4; i++) s[i][0] = s[i][1] = s[i][2] = s[i][3] = 0.f;
        #pragma unroll 8
        for (int d = 0; d < 64; d++) {
            float4 qv = *(const float4*)&Qst[d * FA_PAD + ty * 4];
            float4 kv = *(const float4*)&Kst[d * FA_PAD + tx * 4];
            float qa[4] = {qv.x, qv.y, qv.z, qv.w};
            float ka[4] = {kv.x, kv.y, kv.z, kv.w};
            #pragma unroll
            for (int i = 0; i < 4; i++)
                #pragma unroll
                for (int j = 0; j < 4; j++) s[i][j] += qa[i] * ka[j];
        }

        #pragma unroll
        for (int i = 0; i < 4; i++) {
            float tm = fmaxf(fmaxf(s[i][0], s[i][1]), fmaxf(s[i][2], s[i][3]));
            #pragma unroll
            for (int o = 8; o; o >>= 1) tm = fmaxf(tm, __shfl_xor_sync(0xffffffffu, tm, o));
            float mn = fmaxf(m0[i], tm);
            float corr = __expf(m0[i] - mn);
            float ps = 0.f;
            #pragma unroll
            for (int j = 0; j < 4; j++) {
                float p = __expf(s[i][j] - mn);
                ps += p;
                Pst[(tx * 4 + j) * FA_PAD + ty * 4 + i] = p;
            }
            #pragma unroll
            for (int o = 8; o; o >>= 1) ps += __shfl_xor_sync(0xffffffffu, ps, o);
            l0[i] = l0[i] * corr + ps;
            m0[i] = mn;
            acc[i][0] *= corr; acc[i][1] *= corr;
            acc[i][2] *= corr; acc[i][3] *= corr;
        }
        __syncthreads();

        #pragma unroll 8
        for (int kk = 0; kk < 64; kk++) {
            float4 pv = *(const float4*)&Pst[kk * FA_PAD + ty * 4];
            float4 vv = *(const float4*)&Vs[kk * FA_PAD + tx * 4];
            float pa[4] = {pv.x, pv.y, pv.z, pv.w};
            float va[4] = {vv.x, vv.y, vv.z, vv.w};
            #pragma unroll
            for (int i = 0; i < 4; i++)
                #pragma unroll
                for (int j = 0; j < 4; j++) acc[i][j] += pa[i] * va[j];
        }
        __syncthreads();
    }

    #pragma unroll
    for (int i = 0; i < 4; i++) {
        float inv = 1.f / l0[i];
        int srow = qb + ty * 4 + i;
        float4 o = {acc[i][0] * inv, acc[i][1] * inv, acc[i][2] * inv, acc[i][3] * inv};
        *(float4*)&O[(size_t)srow * HID + h * HD + tx * 4] = o;
    }
}

// ---------------- launch ---------------------------------------------------
extern "C" void kernel_launch(void* const* d_in, const int* in_sizes, int n_in,
                              void* d_out, int out_size)
{
    const float* img   = (const float*)d_in[0];
    const float* txt   = (const float*)d_in[1];
    const float* pe    = (const float*)d_in[2];
    const float* vec   = (const float*)d_in[3];
    const float* imw   = (const float*)d_in[4];
    const float* imb   = (const float*)d_in[5];
    const float* tmw   = (const float*)d_in[6];
    const float* tmb   = (const float*)d_in[7];
    const float* iqkvw = (const float*)d_in[8];
    const float* iqkvb = (const float*)d_in[9];
    const float* iqs   = (const float*)d_in[10];
    const float* iks   = (const float*)d_in[11];
    const float* projw = (const float*)d_in[12];
    const float* projb = (const float*)d_in[13];
    const float* tqkvw = (const float*)d_in[14];
    const float* tqkvb = (const float*)d_in[15];
    const float* tqs   = (const float*)d_in[16];
    const float* tks   = (const float*)d_in[17];
    const float* w1    = (const float*)d_in[18];
    const float* b1    = (const float*)d_in[19];
    const float* w2    = (const float*)d_in[20];
    const float* b2    = (const float*)d_in[21];

    float *mod, *imgm, *txtm, *qi, *qt, *q, *k, *v, *attn, *img2, *ln2, *mlp;
    float *wt_iqkv, *wt_tqkv, *wt_proj, *wt_w1, *wt_w2;
    cudaGetSymbolAddress((void**)&mod,  g_mod);
    cudaGetSymbolAddress((void**)&imgm, g_imgm);
    cudaGetSymbolAddress((void**)&txtm, g_txtm);
    cudaGetSymbolAddress((void**)&qi,   g_qkv_img);
    cudaGetSymbolAddress((void**)&qt,   g_qkv_txt);
    cudaGetSymbolAddress((void**)&q,    g_q);
    cudaGetSymbolAddress((void**)&k,    g_k);
    cudaGetSymbolAddress((void**)&v,    g_v);
    cudaGetSymbolAddress((void**)&attn, g_attn);
    cudaGetSymbolAddress((void**)&img2, g_img2);
    cudaGetSymbolAddress((void**)&ln2,  g_ln2);
    cudaGetSymbolAddress((void**)&mlp,  g_mlp);
    cudaGetSymbolAddress((void**)&wt_iqkv, g_wt_iqkv);
    cudaGetSymbolAddress((void**)&wt_tqkv, g_wt_tqkv);
    cudaGetSymbolAddress((void**)&wt_proj, g_wt_proj);
    cudaGetSymbolAddress((void**)&wt_w1,   g_wt_w1);
    cudaGetSymbolAddress((void**)&wt_w2,   g_wt_w2);

    cudaFuncSetAttribute(flash_kernel, cudaFuncAttributeMaxDynamicSharedMemorySize,
                         4 * 64 * FA_PAD * 4);
    cudaFuncSetAttribute(mma_gemm<0>, cudaFuncAttributeMaxDynamicSharedMemorySize, MM_SMEM);
    cudaFuncSetAttribute(mma_gemm<1>, cudaFuncAttributeMaxDynamicSharedMemorySize, MM_SMEM);
    cudaFuncSetAttribute(mma_gemm<2>, cudaFuncAttributeMaxDynamicSharedMemorySize, MM_SMEM);

    // 0) weight transposes ([K,N] -> [N,K])
    { dim3 b(32, 8);
      transpose_k<<<dim3(96, 32),  b>>>(iqkvw, wt_iqkv, HID, 3 * HID);
      transpose_k<<<dim3(96, 32),  b>>>(tqkvw, wt_tqkv, HID, 3 * HID);
      transpose_k<<<dim3(32, 32),  b>>>(projw, wt_proj, HID, HID);
      transpose_k<<<dim3(128, 32), b>>>(w1,    wt_w1,   HID, MLPD);
      transpose_k<<<dim3(32, 128), b>>>(w2,    wt_w2,   MLPD, HID); }
    // 1) modulation vectors
    mod_kernel<<<96, 128>>>(vec, imw, imb, tmw, tmb, mod);
    // 2) LN + modulate (img, txt)
    ln_mod_kernel<<<LI, 256>>>(img, mod, 0, 1024, imgm);
    ln_mod_kernel<<<LT, 256>>>(txt, mod, 6144, 7168, txtm);
    // 3) QKV GEMMs (tf32 mma)
    { dim3 g(24, 16); mma_gemm<0><<<g, 256, MM_SMEM>>>(imgm, wt_iqkv, iqkvb, nullptr, nullptr, qi, 3 * HID, HID); }
    { dim3 g(24, 2);  mma_gemm<0><<<g, 256, MM_SMEM>>>(txtm, wt_tqkv, tqkvb, nullptr, nullptr, qt, 3 * HID, HID); }
    // 4) rms-norm + rope + head layout
    build_qkv_kernel<<<LTOT, 256>>>(qi, qt, iqs, iks, tqs, tks, pe, q, k, v);
    // 5) attention (fp32 flash)
    { dim3 g(LTOT / 64, NHEAD);
      flash_kernel<<<g, 256, 4 * 64 * FA_PAD * 4>>>(q, k, v, attn); }
    // 6) proj + gated residual (img rows only)
    { dim3 g(8, 16); mma_gemm<2><<<g, 256, MM_SMEM>>>(attn + (size_t)LT * HID, wt_proj, projb,
                                                      img, mod + 2048, img2, HID, HID); }
    // 7) LN2 + modulate
    ln_mod_kernel<<<LI, 256>>>(img2, mod, 3072, 4096, ln2);
    // 8) MLP (tf32 mma)
    { dim3 g(32, 16); mma_gemm<1><<<g, 256, MM_SMEM>>>(ln2, wt_w1, b1, nullptr, nullptr, mlp, MLPD, HID); }
    { dim3 g(8, 16);  mma_gemm<2><<<g, 256, MM_SMEM>>>(mlp, wt_w2, b2, img2, mod + 5120,
                                                       (float*)d_out, HID, MLPD); }
}

// round 4
// speedup vs baseline: 3.1467x; 1.4816x over previous
#include <cuda_runtime.h>
#include <cstdint>
#include <math.h>

// Problem constants
#define HID   1024
#define LT    256
#define LI    2048
#define LTOT  2304
#define NHEAD 16
#define HD    64
#define MLPD  4096

// ---------------- scratch (device globals; no cudaMalloc allowed) ----------
__device__ float g_mod[12288];
__device__ float g_imgm[LI * HID];
__device__ float g_txtm[LT * HID];
__device__ float g_qkv_img[LI * 3 * HID];
__device__ float g_qkv_txt[LT * 3 * HID];
__device__ float g_q[NHEAD * LTOT * HD];
__device__ float g_k[NHEAD * LTOT * HD];
__device__ float g_v[NHEAD * LTOT * HD];
__device__ float g_attn[LTOT * HID];
__device__ float g_img2[LI * HID];
__device__ float g_ln2[LI * HID];
__device__ float g_mlp[LI * MLPD];
// transposed weights [N,K]
__device__ float g_wt_iqkv[3 * HID * HID];
__device__ float g_wt_tqkv[3 * HID * HID];
__device__ float g_wt_proj[HID * HID];
__device__ float g_wt_w1[MLPD * HID];
__device__ float g_wt_w2[HID * MLPD];

// ---------------- PTX helpers ----------------------------------------------
__device__ __forceinline__ uint32_t smem_u32(const void* p) {
    uint32_t a;
    asm("{ .reg .u64 t; cvta.to.shared.u64 t, %1; cvt.u32.u64 %0, t; }" : "=r"(a) : "l"(p));
    return a;
}
#define CP_ASYNC16(dst, src) \
    asm volatile("cp.async.cg.shared.global [%0], [%1], 16;" :: "r"(dst), "l"(src))
#define CP_COMMIT() asm volatile("cp.async.commit_group;")
#define CP_WAIT(n)  asm volatile("cp.async.wait_group %0;" :: "n"(n))

#define LDSM_X4(r, a)                                                          \
    asm volatile("ldmatrix.sync.aligned.m8n8.x4.shared.b16 {%0,%1,%2,%3}, [%4];" \
        : "=r"((r)[0]), "=r"((r)[1]), "=r"((r)[2]), "=r"((r)[3]) : "r"(a))

#define CVT_TF32(x) asm volatile("cvt.rna.tf32.f32 %0, %0;" : "+r"(x))

#define MMA_TF32(d, a, b0, b1)                                                 \
    asm volatile("mma.sync.aligned.m16n8k8.row.col.f32.tf32.tf32.f32 "         \
        "{%0,%1,%2,%3}, {%4,%5,%6,%7}, {%8,%9}, {%0,%1,%2,%3};"                \
        : "+f"((d)[0]), "+f"((d)[1]), "+f"((d)[2]), "+f"((d)[3])               \
        : "r"((a)[0]), "r"((a)[1]), "r"((a)[2]), "r"((a)[3]),                  \
          "r"(b0), "r"(b1))

// ---------------- weight transpose: W[K,N] -> WT[N,K] ----------------------
__global__ void transpose_k(const float* __restrict__ W, float* __restrict__ WT,
                            int K, int N)
{
    __shared__ float t[32][33];
    int n0 = blockIdx.x * 32, k0 = blockIdx.y * 32;
    int tx = threadIdx.x, ty = threadIdx.y;
    #pragma unroll
    for (int i = 0; i < 32; i += 8)
        t[ty + i][tx] = W[(size_t)(k0 + ty + i) * N + n0 + tx];
    __syncthreads();
    #pragma unroll
    for (int i = 0; i < 32; i += 8)
        WT[(size_t)(n0 + ty + i) * K + k0 + tx] = t[tx][ty + i];
}

// ---------------- modulation: silu(vec) @ mod_w + mod_b --------------------
__global__ void mod_kernel(const float* __restrict__ vec,
                           const float* __restrict__ imw, const float* __restrict__ imb,
                           const float* __restrict__ tmw, const float* __restrict__ tmb,
                           float* __restrict__ mod)
{
    __shared__ float sv[HID];
    int tid = threadIdx.x;
    for (int i = tid; i < HID; i += 128) {
        float x = vec[i];
        sv[i] = x / (1.f + expf(-x));
    }
    __syncthreads();
    int blk = blockIdx.x;
    bool is_img = blk < 48;
    int col = (is_img ? blk : blk - 48) * 128 + tid;
    const float* w = is_img ? imw : tmw;
    const float* b = is_img ? imb : tmb;
    float* out = mod + (is_img ? 0 : 6144);
    float a0 = 0.f, a1 = 0.f, a2 = 0.f, a3 = 0.f;
    for (int d = 0; d < HID; d += 4) {
        a0 += sv[d + 0] * w[(d + 0) * 6144 + col];
        a1 += sv[d + 1] * w[(d + 1) * 6144 + col];
        a2 += sv[d + 2] * w[(d + 2) * 6144 + col];
        a3 += sv[d + 3] * w[(d + 3) * 6144 + col];
    }
    out[col] = b[col] + ((a0 + a1) + (a2 + a3));
}

// ---------------- fused LayerNorm + modulate -------------------------------
__global__ void ln_mod_kernel(const float* __restrict__ x,
                              const float* __restrict__ mod,
                              int shift_off, int scale_off,
                              float* __restrict__ out)
{
    __shared__ float red[2][8];
    int row = blockIdx.x, tid = threadIdx.x;
    float4 xv = ((const float4*)(x + row * HID))[tid];
    float s  = xv.x + xv.y + xv.z + xv.w;
    float s2 = xv.x * xv.x + xv.y * xv.y + xv.z * xv.z + xv.w * xv.w;
    #pragma unroll
    for (int o = 16; o; o >>= 1) {
        s  += __shfl_xor_sync(0xffffffffu, s,  o);
        s2 += __shfl_xor_sync(0xffffffffu, s2, o);
    }
    int warp = tid >> 5, lane = tid & 31;
    if (lane == 0) { red[0][warp] = s; red[1][warp] = s2; }
    __syncthreads();
    s = 0.f; s2 = 0.f;
    #pragma unroll
    for (int w = 0; w < 8; w++) { s += red[0][w]; s2 += red[1][w]; }
    float mean = s * (1.f / HID);
    float var  = s2 * (1.f / HID) - mean * mean;
    float rs = rsqrtf(var + 1e-6f);
    int c = tid * 4;
    float4 sc = *(const float4*)(mod + scale_off + c);
    float4 sh = *(const float4*)(mod + shift_off + c);
    float4 o;
    o.x = (xv.x - mean) * rs * (1.f + sc.x) + sh.x;
    o.y = (xv.y - mean) * rs * (1.f + sc.y) + sh.y;
    o.z = (xv.z - mean) * rs * (1.f + sc.z) + sh.z;
    o.w = (xv.w - mean) * rs * (1.f + sc.w) + sh.w;
    ((float4*)(out + row * HID))[tid] = o;
}

// ---------------- tf32 mma.sync GEMM: C[M,N] = A[M,K] @ BT[N,K]^T ----------
__device__ __forceinline__ float gelu_tanh(float x)
{
    return 0.5f * x * (1.f + tanhf(0.7978845608028654f * (x + 0.044715f * x * x * x)));
}

#define ROWB 144                       // bytes per padded smem row (32+4 floats)
#define TILEB (128 * ROWB)             // 18432 B per tile
#define MM_SMEM (4 * TILEB)            // A0 A1 B0 B1 = 73728 B

__device__ __forceinline__ void mm_load_tile(uint32_t sbase, const float* __restrict__ g,
                                             int K, int k0)
{
    int tid = threadIdx.x;
    #pragma unroll
    for (int i = 0; i < 4; i++) {
        int id = tid + i * 256;
        int r = id >> 3, c = id & 7;
        uint32_t dst = sbase + r * ROWB + c * 16;
        const float* src = g + (size_t)r * K + k0 + c * 4;
        CP_ASYNC16(dst, src);
    }
}

template <int EPI>
__global__ void __launch_bounds__(256) mma_gemm(
    const float* __restrict__ A, const float* __restrict__ BT,
    const float* __restrict__ bias, const float* __restrict__ res,
    const float* __restrict__ gate, float* __restrict__ C,
    int N, int K)
{
    extern __shared__ char smem[];
    uint32_t su = smem_u32(smem);
    uint32_t sA[2] = { su,              su + TILEB };
    uint32_t sB[2] = { su + 2 * TILEB,  su + 3 * TILEB };

    int tid = threadIdx.x;
    int wid = tid >> 5, lane = tid & 31;
    int warp_m = wid & 3, warp_n = wid >> 2;
    int row0 = blockIdx.y * 128;
    int col0 = blockIdx.x * 128;
    const float* Ab = A + (size_t)row0 * K;
    const float* Bb = BT + (size_t)col0 * K;

    float acc[2][8][4];
    #pragma unroll
    for (int mt = 0; mt < 2; mt++)
        #pragma unroll
        for (int nt = 0; nt < 8; nt++)
            #pragma unroll
            for (int e = 0; e < 4; e++) acc[mt][nt][e] = 0.f;

    uint32_t aoff = (uint32_t)((warp_m * 32 + (lane & 15)) * ROWB + ((lane >> 4) & 1) * 16);
    uint32_t boff = (uint32_t)((warp_n * 64 + (lane & 7) + ((lane >> 4) & 1) * 8) * ROWB
                               + (lane & 8 ? 16 : 0));

    int T = K >> 5;
    mm_load_tile(sA[0], Ab, K, 0);
    mm_load_tile(sB[0], Bb, K, 0);
    CP_COMMIT();

    for (int t = 0; t < T; t++) {
        int b = t & 1;
        if (t + 1 < T) {
            mm_load_tile(sA[b ^ 1], Ab, K, (t + 1) * 32);
            mm_load_tile(sB[b ^ 1], Bb, K, (t + 1) * 32);
            CP_COMMIT();
            CP_WAIT(1);
        } else {
            CP_WAIT(0);
        }
        __syncthreads();

        uint32_t Abase = sA[b] + aoff;
        uint32_t Bbase = sB[b] + boff;
        #pragma unroll
        for (int ks = 0; ks < 4; ks++) {
            uint32_t af[2][4], bf[4][4];
            LDSM_X4(af[0], Abase + ks * 32);
            LDSM_X4(af[1], Abase + 16 * ROWB + ks * 32);
            #pragma unroll
            for (int p = 0; p < 4; p++)
                LDSM_X4(bf[p], Bbase + p * 16 * ROWB + ks * 32);
            #pragma unroll
            for (int mt = 0; mt < 2; mt++)
                #pragma unroll
                for (int e = 0; e < 4; e++) CVT_TF32(af[mt][e]);
            #pragma unroll
            for (int p = 0; p < 4; p++)
                #pragma unroll
                for (int e = 0; e < 4; e++) CVT_TF32(bf[p][e]);
            #pragma unroll
            for (int mt = 0; mt < 2; mt++)
                #pragma unroll
                for (int nt = 0; nt < 8; nt++) {
                    uint32_t b0 = bf[nt >> 1][(nt & 1) ? 2 : 0];
                    uint32_t b1 = bf[nt >> 1][(nt & 1) ? 3 : 1];
                    MMA_TF32(acc[mt][nt], af[mt], b0, b1);
                }
        }
        __syncthreads();
    }

    int qr = lane >> 2, qc = (lane & 3) * 2;
    #pragma unroll
    for (int mt = 0; mt < 2; mt++) {
        int gr0 = row0 + warp_m * 32 + mt * 16 + qr;
        #pragma unroll
        for (int nt = 0; nt < 8; nt++) {
            int gc = col0 + warp_n * 64 + nt * 8 + qc;
            float2 bv = *(const float2*)(bias + gc);
            #pragma unroll
            for (int h = 0; h < 2; h++) {
                int gr = gr0 + h * 8;
                float2 v;
                v.x = acc[mt][nt][2 * h + 0] + bv.x;
                v.y = acc[mt][nt][2 * h + 1] + bv.y;
                if (EPI == 1) {
                    v.x = gelu_tanh(v.x);
                    v.y = gelu_tanh(v.y);
                } else if (EPI == 2) {
                    float2 rr = *(const float2*)(res + (size_t)gr * N + gc);
                    float2 gg = *(const float2*)(gate + gc);
                    v.x = rr.x + gg.x * v.x;
                    v.y = rr.y + gg.y * v.y;
                }
                *(float2*)&C[(size_t)gr * N + gc] = v;
            }
        }
    }
}

// ---------------- build q/k/v: rms-norm + rope + head layout ---------------
__global__ void build_qkv_kernel(const float* __restrict__ qkv_img,
                                 const float* __restrict__ qkv_txt,
                                 const float* __restrict__ iqs, const float* __restrict__ iks,
                                 const float* __restrict__ tqs, const float* __restrict__ tks,
                                 const float* __restrict__ pe,
                                 float* __restrict__ q, float* __restrict__ k,
                                 float* __restrict__ v)
{
    int s = blockIdx.x;
    int warp = threadIdx.x >> 5, lane = threadIdx.x & 31;
    bool is_txt = s < LT;
    const float* src = is_txt ? (qkv_txt + (size_t)s * 3072)
                              : (qkv_img + (size_t)(s - LT) * 3072);
    for (int u = warp; u < 48; u += 8) {
        int which = u >> 4;       // 0=q 1=k 2=v
        int h = u & 15;
        const float* base = src + which * HID + h * HD;
        float x0 = base[2 * lane], x1 = base[2 * lane + 1];
        size_t didx = ((size_t)h * LTOT + s) * HD + 2 * lane;
        if (which == 2) {
            v[didx] = x0; v[didx + 1] = x1;
        } else {
            float ss = x0 * x0 + x1 * x1;
            #pragma unroll
            for (int o = 16; o; o >>= 1) ss += __shfl_xor_sync(0xffffffffu, ss, o);
            float r = rsqrtf(ss * (1.f / HD) + 1e-6f);
            const float* sc = (which == 0) ? (is_txt ? tqs : iqs)
                                           : (is_txt ? tks : iks);
            x0 *= r * sc[2 * lane];
            x1 *= r * sc[2 * lane + 1];
            const float* p = pe + (size_t)s * 128 + lane * 4;
            float o0 = p[0] * x0 + p[1] * x1;
            float o1 = p[2] * x0 + p[3] * x1;
            if (which == 0) { o0 *= 0.125f; o1 *= 0.125f; }  // fold 1/sqrt(HD)
            float* dst = (which == 0) ? q : k;
            dst[didx] = o0; dst[didx + 1] = o1;
        }
    }
}

// ---------------- tf32 flash attention: BQ=BK=64, HD=64 --------------------
// 4 warps / 128 threads. Only img query rows (qb >= LT). Online softmax with
// register fragments; P routed via smem for the P@V mma.
#define FROW  68                 // floats per padded smem row
#define FROWB 272                // bytes per padded smem row
#define FTILEB (64 * FROWB)      // 17408 B per 64x64 tile
#define FL_SMEM (4 * FTILEB)     // Q, K, Vt, P = 69632 B

__global__ void __launch_bounds__(128) flash_tf32(
    const float* __restrict__ Q, const float* __restrict__ Kg,
    const float* __restrict__ Vg, float* __restrict__ O)
{
    extern __shared__ float sm[];
    float* Qs = sm;                       // [q][d]
    float* Ks = sm + 64 * FROW;           // [k][d]
    float* Vt = sm + 2 * 64 * FROW;       // [d][k]
    float* Ps = sm + 3 * 64 * FROW;       // [q][k]
    uint32_t su = smem_u32(sm);
    uint32_t uQ = su, uK = su + FTILEB, uV = su + 2 * FTILEB, uP = su + 3 * FTILEB;

    int tid = threadIdx.x;
    int wid = tid >> 5, lane = tid & 31;
    int h = blockIdx.y;
    int qb = LT + blockIdx.x * 64;
    const float* Qh = Q + ((size_t)h * LTOT + qb) * HD;
    const float* Kh = Kg + (size_t)h * LTOT * HD;
    const float* Vh = Vg + (size_t)h * LTOT * HD;

    // load Q tile [64][64] row-major
    #pragma unroll
    for (int i = 0; i < 8; i++) {
        int f = tid + i * 128;
        int r = f >> 4, c = (f & 15) * 4;
        *(float4*)&Qs[r * FROW + c] = *(const float4*)(Qh + r * HD + c);
    }

    uint32_t aoff = (uint32_t)((wid * 16 + (lane & 15)) * FROWB + ((lane >> 4) & 1) * 16);
    uint32_t boff = (uint32_t)(((lane & 7) + ((lane >> 4) & 1) * 8) * FROWB
                               + ((lane & 8) ? 16 : 0));

    float m0 = -1e30f, m1 = -1e30f, ls0 = 0.f, ls1 = 0.f;
    float oacc[8][4];
    #pragma unroll
    for (int nt = 0; nt < 8; nt++)
        #pragma unroll
        for (int e = 0; e < 4; e++) oacc[nt][e] = 0.f;

    int prow0 = wid * 16 + (lane >> 2);
    int pcol  = 2 * (lane & 3);

    for (int kb = 0; kb < LTOT; kb += 64) {
        __syncthreads();
        // load K [k][d] and V transposed [d][k]
        #pragma unroll
        for (int i = 0; i < 8; i++) {
            int f = tid + i * 128;
            int r = f >> 4, c = (f & 15) * 4;
            *(float4*)&Ks[r * FROW + c] = *(const float4*)(Kh + (size_t)(kb + r) * HD + c);
            float4 vv = *(const float4*)(Vh + (size_t)(kb + r) * HD + c);
            Vt[(c + 0) * FROW + r] = vv.x;
            Vt[(c + 1) * FROW + r] = vv.y;
            Vt[(c + 2) * FROW + r] = vv.z;
            Vt[(c + 3) * FROW + r] = vv.w;
        }
        __syncthreads();

        // S = Q @ K^T  (per warp: 16 x 64)
        float sacc[8][4];
        #pragma unroll
        for (int nt = 0; nt < 8; nt++)
            #pragma unroll
            for (int e = 0; e < 4; e++) sacc[nt][e] = 0.f;
        #pragma unroll
        for (int ks = 0; ks < 8; ks++) {
            uint32_t af[4], bf[4][4];
            LDSM_X4(af, uQ + aoff + ks * 32);
            #pragma unroll
            for (int p = 0; p < 4; p++)
                LDSM_X4(bf[p], uK + boff + p * 16 * FROWB + ks * 32);
            #pragma unroll
            for (int e = 0; e < 4; e++) CVT_TF32(af[e]);
            #pragma unroll
            for (int p = 0; p < 4; p++)
                #pragma unroll
                for (int e = 0; e < 4; e++) CVT_TF32(bf[p][e]);
            #pragma unroll
            for (int nt = 0; nt < 8; nt++)
                MMA_TF32(sacc[nt], af, bf[nt >> 1][(nt & 1) ? 2 : 0],
                         bf[nt >> 1][(nt & 1) ? 3 : 1]);
        }

        // online softmax (rows prow0, prow0+8)
        float mx0 = -1e30f, mx1 = -1e30f;
        #pragma unroll
        for (int nt = 0; nt < 8; nt++) {
            mx0 = fmaxf(mx0, fmaxf(sacc[nt][0], sacc[nt][1]));
            mx1 = fmaxf(mx1, fmaxf(sacc[nt][2], sacc[nt][3]));
        }
        mx0 = fmaxf(mx0, __shfl_xor_sync(0xffffffffu, mx0, 1));
        mx0 = fmaxf(mx0, __shfl_xor_sync(0xffffffffu, mx0, 2));
        mx1 = fmaxf(mx1, __shfl_xor_sync(0xffffffffu, mx1, 1));
        mx1 = fmaxf(mx1, __shfl_xor_sync(0xffffffffu, mx1, 2));
        float mn0 = fmaxf(m0, mx0), mn1 = fmaxf(m1, mx1);
        float c0 = __expf(m0 - mn0), c1 = __expf(m1 - mn1);
        float ps0 = 0.f, ps1 = 0.f;
        #pragma unroll
        for (int nt = 0; nt < 8; nt++) {
            float p00 = __expf(sacc[nt][0] - mn0);
            float p01 = __expf(sacc[nt][1] - mn0);
            float p10 = __expf(sacc[nt][2] - mn1);
            float p11 = __expf(sacc[nt][3] - mn1);
            ps0 += p00 + p01; ps1 += p10 + p11;
            int col = nt * 8 + pcol;
            *(float2*)&Ps[prow0 * FROW + col] = make_float2(p00, p01);
            *(float2*)&Ps[(prow0 + 8) * FROW + col] = make_float2(p10, p11);
        }
        ps0 += __shfl_xor_sync(0xffffffffu, ps0, 1);
        ps0 += __shfl_xor_sync(0xffffffffu, ps0, 2);
        ps1 += __shfl_xor_sync(0xffffffffu, ps1, 1);
        ps1 += __shfl_xor_sync(0xffffffffu, ps1, 2);
        ls0 = ls0 * c0 + ps0;
        ls1 = ls1 * c1 + ps1;
        m0 = mn0; m1 = mn1;
        #pragma unroll
        for (int nt = 0; nt < 8; nt++) {
            oacc[nt][0] *= c0; oacc[nt][1] *= c0;
            oacc[nt][2] *= c1; oacc[nt][3] *= c1;
        }
        __syncthreads();

        // O += P @ V   (A = Ps rows of this warp, B = Vt)
        #pragma unroll
        for (int ks = 0; ks < 8; ks++) {
            uint32_t af[4], bf[4][4];
            LDSM_X4(af, uP + aoff + ks * 32);
            #pragma unroll
            for (int p = 0; p < 4; p++)
                LDSM_X4(bf[p], uV + boff + p * 16 * FROWB + ks * 32);
            #pragma unroll
            for (int e = 0; e < 4; e++) CVT_TF32(af[e]);
            #pragma unroll
            for (int p = 0; p < 4; p++)
                #pragma unroll
                for (int e = 0; e < 4; e++) CVT_TF32(bf[p][e]);
            #pragma unroll
            for (int nt = 0; nt < 8; nt++)
                MMA_TF32(oacc[nt], af, bf[nt >> 1][(nt & 1) ? 2 : 0],
                         bf[nt >> 1][(nt & 1) ? 3 : 1]);
        }
    }

    float inv0 = 1.f / ls0, inv1 = 1.f / ls1;
    int r0 = qb + prow0, r1 = r0 + 8;
    #pragma unroll
    for (int nt = 0; nt < 8; nt++) {
        int col = h * HD + nt * 8 + pcol;
        *(float2*)&O[(size_t)r0 * HID + col] =
            make_float2(oacc[nt][0] * inv0, oacc[nt][1] * inv0);
        *(float2*)&O[(size_t)r1 * HID + col] =
            make_float2(oacc[nt][2] * inv1, oacc[nt][3] * inv1);
    }
}

// ---------------- launch ---------------------------------------------------
extern "C" void kernel_launch(void* const* d_in, const int* in_sizes, int n_in,
                              void* d_out, int out_size)
{
    const float* img   = (const float*)d_in[0];
    const float* txt   = (const float*)d_in[1];
    const float* pe    = (const float*)d_in[2];
    const float* vec   = (const float*)d_in[3];
    const float* imw   = (const float*)d_in[4];
    const float* imb   = (const float*)d_in[5];
    const float* tmw   = (const float*)d_in[6];
    const float* tmb   = (const float*)d_in[7];
    const float* iqkvw = (const float*)d_in[8];
    const float* iqkvb = (const float*)d_in[9];
    const float* iqs   = (const float*)d_in[10];
    const float* iks   = (const float*)d_in[11];
    const float* projw = (const float*)d_in[12];
    const float* projb = (const float*)d_in[13];
    const float* tqkvw = (const float*)d_in[14];
    const float* tqkvb = (const float*)d_in[15];
    const float* tqs   = (const float*)d_in[16];
    const float* tks   = (const float*)d_in[17];
    const float* w1    = (const float*)d_in[18];
    const float* b1    = (const float*)d_in[19];
    const float* w2    = (const float*)d_in[20];
    const float* b2    = (const float*)d_in[21];

    float *mod, *imgm, *txtm, *qi, *qt, *q, *k, *v, *attn, *img2, *ln2, *mlp;
    float *wt_iqkv, *wt_tqkv, *wt_proj, *wt_w1, *wt_w2;
    cudaGetSymbolAddress((void**)&mod,  g_mod);
    cudaGetSymbolAddress((void**)&imgm, g_imgm);
    cudaGetSymbolAddress((void**)&txtm, g_txtm);
    cudaGetSymbolAddress((void**)&qi,   g_qkv_img);
    cudaGetSymbolAddress((void**)&qt,   g_qkv_txt);
    cudaGetSymbolAddress((void**)&q,    g_q);
    cudaGetSymbolAddress((void**)&k,    g_k);
    cudaGetSymbolAddress((void**)&v,    g_v);
    cudaGetSymbolAddress((void**)&attn, g_attn);
    cudaGetSymbolAddress((void**)&img2, g_img2);
    cudaGetSymbolAddress((void**)&ln2,  g_ln2);
    cudaGetSymbolAddress((void**)&mlp,  g_mlp);
    cudaGetSymbolAddress((void**)&wt_iqkv, g_wt_iqkv);
    cudaGetSymbolAddress((void**)&wt_tqkv, g_wt_tqkv);
    cudaGetSymbolAddress((void**)&wt_proj, g_wt_proj);
    cudaGetSymbolAddress((void**)&wt_w1,   g_wt_w1);
    cudaGetSymbolAddress((void**)&wt_w2,   g_wt_w2);

    cudaFuncSetAttribute(flash_tf32, cudaFuncAttributeMaxDynamicSharedMemorySize, FL_SMEM);
    cudaFuncSetAttribute(mma_gemm<0>, cudaFuncAttributeMaxDynamicSharedMemorySize, MM_SMEM);
    cudaFuncSetAttribute(mma_gemm<1>, cudaFuncAttributeMaxDynamicSharedMemorySize, MM_SMEM);
    cudaFuncSetAttribute(mma_gemm<2>, cudaFuncAttributeMaxDynamicSharedMemorySize, MM_SMEM);

    // 0) weight transposes ([K,N] -> [N,K])
    { dim3 b(32, 8);
      transpose_k<<<dim3(96, 32),  b>>>(iqkvw, wt_iqkv, HID, 3 * HID);
      transpose_k<<<dim3(96, 32),  b>>>(tqkvw, wt_tqkv, HID, 3 * HID);
      transpose_k<<<dim3(32, 32),  b>>>(projw, wt_proj, HID, HID);
      transpose_k<<<dim3(128, 32), b>>>(w1,    wt_w1,   HID, MLPD);
      transpose_k<<<dim3(32, 128), b>>>(w2,    wt_w2,   MLPD, HID); }
    // 1) modulation vectors
    mod_kernel<<<96, 128>>>(vec, imw, imb, tmw, tmb, mod);
    // 2) LN + modulate (img, txt)
    ln_mod_kernel<<<LI, 256>>>(img, mod, 0, 1024, imgm);
    ln_mod_kernel<<<LT, 256>>>(txt, mod, 6144, 7168, txtm);
    // 3) QKV GEMMs (tf32 mma)
    { dim3 g(24, 16); mma_gemm<0><<<g, 256, MM_SMEM>>>(imgm, wt_iqkv, iqkvb, nullptr, nullptr, qi, 3 * HID, HID); }
    { dim3 g(24, 2);  mma_gemm<0><<<g, 256, MM_SMEM>>>(txtm, wt_tqkv, tqkvb, nullptr, nullptr, qt, 3 * HID, HID); }
    // 4) rms-norm + rope + head layout
    build_qkv_kernel<<<LTOT, 256>>>(qi, qt, iqs, iks, tqs, tks, pe, q, k, v);
    // 5) attention (tf32 flash, img queries only)
    { dim3 g(LI / 64, NHEAD);
      flash_tf32<<<g, 128, FL_SMEM>>>(q, k, v, attn); }
    // 6) proj + gated residual (img rows only)
    { dim3 g(8, 16); mma_gemm<2><<<g, 256, MM_SMEM>>>(attn + (size_t)LT * HID, wt_proj, projb,
                                                      img, mod + 2048, img2, HID, HID); }
    // 7) LN2 + modulate
    ln_mod_kernel<<<LI, 256>>>(img2, mod, 3072, 4096, ln2);
    // 8) MLP (tf32 mma)
    { dim3 g(32, 16); mma_gemm<1><<<g, 256, MM_SMEM>>>(ln2, wt_w1, b1, nullptr, nullptr, mlp, MLPD, HID); }
    { dim3 g(8, 16);  mma_gemm<2><<<g, 256, MM_SMEM>>>(mlp, wt_w2, b2, img2, mod + 5120,
                                                       (float*)d_out, HID, MLPD); }
}

// round 5
// speedup vs baseline: 3.7182x; 1.1816x over previous
#include <cuda_runtime.h>
#include <cstdint>
#include <math.h>

// Problem constants
#define HID   1024
#define LT    256
#define LI    2048
#define LTOT  2304
#define NHEAD 16
#define HD    64
#define MLPD  4096

// ---------------- scratch (device globals; no cudaMalloc allowed) ----------
__device__ float g_mod[12288];
__device__ float g_imgm[LI * HID];
__device__ float g_txtm[LT * HID];
__device__ float g_qkv_img[LI * 3 * HID];
__device__ float g_qkv_txt[LT * 3 * HID];
__device__ float g_q[NHEAD * LTOT * HD];
__device__ float g_k[NHEAD * LTOT * HD];
__device__ float g_v[NHEAD * LTOT * HD];
__device__ float g_attn[LTOT * HID];
__device__ float g_img2[LI * HID];
__device__ float g_ln2[LI * HID];
__device__ float g_mlp[LI * MLPD];
// transposed weights [N,K]
__device__ float g_wt_iqkv[3 * HID * HID];
__device__ float g_wt_tqkv[3 * HID * HID];
__device__ float g_wt_proj[HID * HID];
__device__ float g_wt_w1[MLPD * HID];
__device__ float g_wt_w2[HID * MLPD];

// ---------------- PTX helpers ----------------------------------------------
__device__ __forceinline__ uint32_t smem_u32(const void* p) {
    uint32_t a;
    asm("{ .reg .u64 t; cvta.to.shared.u64 t, %1; cvt.u32.u64 %0, t; }" : "=r"(a) : "l"(p));
    return a;
}
#define CP_ASYNC16(dst, src) \
    asm volatile("cp.async.cg.shared.global [%0], [%1], 16;" :: "r"(dst), "l"(src))
#define CP_COMMIT() asm volatile("cp.async.commit_group;")
#define CP_WAIT(n)  asm volatile("cp.async.wait_group %0;" :: "n"(n))

#define LDSM_X4(r, a)                                                          \
    asm volatile("ldmatrix.sync.aligned.m8n8.x4.shared.b16 {%0,%1,%2,%3}, [%4];" \
        : "=r"((r)[0]), "=r"((r)[1]), "=r"((r)[2]), "=r"((r)[3]) : "r"(a))

#define CVT_TF32(x) asm volatile("cvt.rna.tf32.f32 %0, %0;" : "+r"(x))

__device__ __forceinline__ float rnd_tf32(float x) {
    uint32_t u = __float_as_uint(x);
    asm("cvt.rna.tf32.f32 %0, %0;" : "+r"(u));
    return __uint_as_float(u);
}

#define MMA_TF32(d, a, b0, b1)                                                 \
    asm volatile("mma.sync.aligned.m16n8k8.row.col.f32.tf32.tf32.f32 "         \
        "{%0,%1,%2,%3}, {%4,%5,%6,%7}, {%8,%9}, {%0,%1,%2,%3};"                \
        : "+f"((d)[0]), "+f"((d)[1]), "+f"((d)[2]), "+f"((d)[3])               \
        : "r"((a)[0]), "r"((a)[1]), "r"((a)[2]), "r"((a)[3]),                  \
          "r"(b0), "r"(b1))

// ---------------- weight transpose + tf32 round: W[K,N] -> WT[N,K] ---------
__global__ void transpose_k(const float* __restrict__ W, float* __restrict__ WT,
                            int K, int N)
{
    __shared__ float t[32][33];
    int n0 = blockIdx.x * 32, k0 = blockIdx.y * 32;
    int tx = threadIdx.x, ty = threadIdx.y;
    #pragma unroll
    for (int i = 0; i < 32; i += 8)
        t[ty + i][tx] = W[(size_t)(k0 + ty + i) * N + n0 + tx];
    __syncthreads();
    #pragma unroll
    for (int i = 0; i < 32; i += 8)
        WT[(size_t)(n0 + ty + i) * K + k0 + tx] = rnd_tf32(t[tx][ty + i]);
}

// ---------------- modulation: silu(vec) @ mod_w + mod_b --------------------
__global__ void mod_kernel(const float* __restrict__ vec,
                           const float* __restrict__ imw, const float* __restrict__ imb,
                           const float* __restrict__ tmw, const float* __restrict__ tmb,
                           float* __restrict__ mod)
{
    __shared__ float sv[HID];
    int tid = threadIdx.x;
    for (int i = tid; i < HID; i += 128) {
        float x = vec[i];
        sv[i] = x / (1.f + expf(-x));
    }
    __syncthreads();
    int blk = blockIdx.x;
    bool is_img = blk < 48;
    int col = (is_img ? blk : blk - 48) * 128 + tid;
    const float* w = is_img ? imw : tmw;
    const float* b = is_img ? imb : tmb;
    float* out = mod + (is_img ? 0 : 6144);
    float a0 = 0.f, a1 = 0.f, a2 = 0.f, a3 = 0.f;
    for (int d = 0; d < HID; d += 4) {
        a0 += sv[d + 0] * w[(d + 0) * 6144 + col];
        a1 += sv[d + 1] * w[(d + 1) * 6144 + col];
        a2 += sv[d + 2] * w[(d + 2) * 6144 + col];
        a3 += sv[d + 3] * w[(d + 3) * 6144 + col];
    }
    out[col] = b[col] + ((a0 + a1) + (a2 + a3));
}

// ---------------- fused LayerNorm + modulate (tf32-rounded output) ---------
__global__ void ln_mod_kernel(const float* __restrict__ x,
                              const float* __restrict__ mod,
                              int shift_off, int scale_off,
                              float* __restrict__ out)
{
    __shared__ float red[2][8];
    int row = blockIdx.x, tid = threadIdx.x;
    float4 xv = ((const float4*)(x + row * HID))[tid];
    float s  = xv.x + xv.y + xv.z + xv.w;
    float s2 = xv.x * xv.x + xv.y * xv.y + xv.z * xv.z + xv.w * xv.w;
    #pragma unroll
    for (int o = 16; o; o >>= 1) {
        s  += __shfl_xor_sync(0xffffffffu, s,  o);
        s2 += __shfl_xor_sync(0xffffffffu, s2, o);
    }
    int warp = tid >> 5, lane = tid & 31;
    if (lane == 0) { red[0][warp] = s; red[1][warp] = s2; }
    __syncthreads();
    s = 0.f; s2 = 0.f;
    #pragma unroll
    for (int w = 0; w < 8; w++) { s += red[0][w]; s2 += red[1][w]; }
    float mean = s * (1.f / HID);
    float var  = s2 * (1.f / HID) - mean * mean;
    float rs = rsqrtf(var + 1e-6f);
    int c = tid * 4;
    float4 sc = *(const float4*)(mod + scale_off + c);
    float4 sh = *(const float4*)(mod + shift_off + c);
    float4 o;
    o.x = rnd_tf32((xv.x - mean) * rs * (1.f + sc.x) + sh.x);
    o.y = rnd_tf32((xv.y - mean) * rs * (1.f + sc.y) + sh.y);
    o.z = rnd_tf32((xv.z - mean) * rs * (1.f + sc.z) + sh.z);
    o.w = rnd_tf32((xv.w - mean) * rs * (1.f + sc.w) + sh.w);
    ((float4*)(out + row * HID))[tid] = o;
}

// ---------------- tf32 mma.sync GEMM: C[M,N] = A[M,K] @ BT[N,K]^T ----------
// Inputs must be pre-rounded to tf32. EPI: 0=+bias; 1=gelu(+bias) [rounded];
// 2 = res + gate[col]*(+bias)
__device__ __forceinline__ float gelu_tanh(float x)
{
    return 0.5f * x * (1.f + tanhf(0.7978845608028654f * (x + 0.044715f * x * x * x)));
}

#define ROWB 144                       // bytes per padded smem row (32+4 floats)
#define TILEB (128 * ROWB)             // 18432 B per tile
#define MM_SMEM (4 * TILEB)            // A0 A1 B0 B1 = 73728 B

__device__ __forceinline__ void mm_load_tile(uint32_t sbase, const float* __restrict__ g,
                                             int K, int k0)
{
    int tid = threadIdx.x;
    #pragma unroll
    for (int i = 0; i < 4; i++) {
        int id = tid + i * 256;
        int r = id >> 3, c = id & 7;
        uint32_t dst = sbase + r * ROWB + c * 16;
        const float* src = g + (size_t)r * K + k0 + c * 4;
        CP_ASYNC16(dst, src);
    }
}

template <int EPI>
__global__ void __launch_bounds__(256) mma_gemm(
    const float* __restrict__ A, const float* __restrict__ BT,
    const float* __restrict__ bias, const float* __restrict__ res,
    const float* __restrict__ gate, float* __restrict__ C,
    int N, int K)
{
    extern __shared__ char smem[];
    uint32_t su = smem_u32(smem);
    uint32_t sA[2] = { su,              su + TILEB };
    uint32_t sB[2] = { su + 2 * TILEB,  su + 3 * TILEB };

    int tid = threadIdx.x;
    int wid = tid >> 5, lane = tid & 31;
    int warp_m = wid & 3, warp_n = wid >> 2;
    int row0 = blockIdx.y * 128;
    int col0 = blockIdx.x * 128;
    const float* Ab = A + (size_t)row0 * K;
    const float* Bb = BT + (size_t)col0 * K;

    float acc[2][8][4];
    #pragma unroll
    for (int mt = 0; mt < 2; mt++)
        #pragma unroll
        for (int nt = 0; nt < 8; nt++)
            #pragma unroll
            for (int e = 0; e < 4; e++) acc[mt][nt][e] = 0.f;

    uint32_t aoff = (uint32_t)((warp_m * 32 + (lane & 15)) * ROWB + ((lane >> 4) & 1) * 16);
    uint32_t boff = (uint32_t)((warp_n * 64 + (lane & 7) + ((lane >> 4) & 1) * 8) * ROWB
                               + (lane & 8 ? 16 : 0));

    int T = K >> 5;
    mm_load_tile(sA[0], Ab, K, 0);
    mm_load_tile(sB[0], Bb, K, 0);
    CP_COMMIT();

    for (int t = 0; t < T; t++) {
        int b = t & 1;
        if (t + 1 < T) {
            mm_load_tile(sA[b ^ 1], Ab, K, (t + 1) * 32);
            mm_load_tile(sB[b ^ 1], Bb, K, (t + 1) * 32);
            CP_COMMIT();
            CP_WAIT(1);
        } else {
            CP_WAIT(0);
        }
        __syncthreads();

        uint32_t Abase = sA[b] + aoff;
        uint32_t Bbase = sB[b] + boff;
        #pragma unroll
        for (int ks = 0; ks < 4; ks++) {
            uint32_t af[2][4], bf[4][4];
            LDSM_X4(af[0], Abase + ks * 32);
            LDSM_X4(af[1], Abase + 16 * ROWB + ks * 32);
            #pragma unroll
            for (int p = 0; p < 4; p++)
                LDSM_X4(bf[p], Bbase + p * 16 * ROWB + ks * 32);
            #pragma unroll
            for (int mt = 0; mt < 2; mt++)
                #pragma unroll
                for (int nt = 0; nt < 8; nt++) {
                    uint32_t b0 = bf[nt >> 1][(nt & 1) ? 2 : 0];
                    uint32_t b1 = bf[nt >> 1][(nt & 1) ? 3 : 1];
                    MMA_TF32(acc[mt][nt], af[mt], b0, b1);
                }
        }
        __syncthreads();
    }

    int qr = lane >> 2, qc = (lane & 3) * 2;
    #pragma unroll
    for (int mt = 0; mt < 2; mt++) {
        int gr0 = row0 + warp_m * 32 + mt * 16 + qr;
        #pragma unroll
        for (int nt = 0; nt < 8; nt++) {
            int gc = col0 + warp_n * 64 + nt * 8 + qc;
            float2 bv = *(const float2*)(bias + gc);
            #pragma unroll
            for (int h = 0; h < 2; h++) {
                int gr = gr0 + h * 8;
                float2 v;
                v.x = acc[mt][nt][2 * h + 0] + bv.x;
                v.y = acc[mt][nt][2 * h + 1] + bv.y;
                if (EPI == 1) {
                    v.x = rnd_tf32(gelu_tanh(v.x));
                    v.y = rnd_tf32(gelu_tanh(v.y));
                } else if (EPI == 2) {
                    float2 rr = *(const float2*)(res + (size_t)gr * N + gc);
                    float2 gg = *(const float2*)(gate + gc);
                    v.x = rr.x + gg.x * v.x;
                    v.y = rr.y + gg.y * v.y;
                }
                *(float2*)&C[(size_t)gr * N + gc] = v;
            }
        }
    }
}

// ---------------- build q/k/v: rms-norm + rope + head layout (tf32) --------
__global__ void build_qkv_kernel(const float* __restrict__ qkv_img,
                                 const float* __restrict__ qkv_txt,
                                 const float* __restrict__ iqs, const float* __restrict__ iks,
                                 const float* __restrict__ tqs, const float* __restrict__ tks,
                                 const float* __restrict__ pe,
                                 float* __restrict__ q, float* __restrict__ k,
                                 float* __restrict__ v)
{
    int s = blockIdx.x;
    int warp = threadIdx.x >> 5, lane = threadIdx.x & 31;
    bool is_txt = s < LT;
    const float* src = is_txt ? (qkv_txt + (size_t)s * 3072)
                              : (qkv_img + (size_t)(s - LT) * 3072);
    for (int u = warp; u < 48; u += 8) {
        int which = u >> 4;       // 0=q 1=k 2=v
        int h = u & 15;
        const float* base = src + which * HID + h * HD;
        float x0 = base[2 * lane], x1 = base[2 * lane + 1];
        size_t didx = ((size_t)h * LTOT + s) * HD + 2 * lane;
        if (which == 2) {
            v[didx] = rnd_tf32(x0); v[didx + 1] = rnd_tf32(x1);
        } else {
            float ss = x0 * x0 + x1 * x1;
            #pragma unroll
            for (int o = 16; o; o >>= 1) ss += __shfl_xor_sync(0xffffffffu, ss, o);
            float r = rsqrtf(ss * (1.f / HD) + 1e-6f);
            const float* sc = (which == 0) ? (is_txt ? tqs : iqs)
                                           : (is_txt ? tks : iks);
            x0 *= r * sc[2 * lane];
            x1 *= r * sc[2 * lane + 1];
            const float* p = pe + (size_t)s * 128 + lane * 4;
            float o0 = p[0] * x0 + p[1] * x1;
            float o1 = p[2] * x0 + p[3] * x1;
            if (which == 0) { o0 *= 0.125f; o1 *= 0.125f; }  // fold 1/sqrt(HD)
            float* dst = (which == 0) ? q : k;
            dst[didx] = rnd_tf32(o0); dst[didx + 1] = rnd_tf32(o1);
        }
    }
}

// ---------------- tf32 flash attention: BQ=128, BK=64, HD=64 ---------------
// 8 warps / 256 threads. Only img query rows (qb >= LT). Inputs pre-rounded.
#define FROW  68                 // floats per padded smem row
#define FROWB 272                // bytes per padded smem row
#define FL_SMEM ((128 + 64 + 64 + 128) * FROWB)   // Q, K, Vt, P = 104448 B

__global__ void __launch_bounds__(256) flash_tf32(
    const float* __restrict__ Q, const float* __restrict__ Kg,
    const float* __restrict__ Vg, float* __restrict__ O)
{
    extern __shared__ float sm[];
    float* Qs = sm;                        // [q][d] 128 rows
    float* Ks = sm + 128 * FROW;           // [k][d] 64 rows
    float* Vt = sm + 192 * FROW;           // [d][k] 64 rows
    float* Ps = sm + 256 * FROW;           // [q][k] 128 rows
    uint32_t su = smem_u32(sm);
    uint32_t uQ = su, uK = su + 128 * FROWB, uV = su + 192 * FROWB, uP = su + 256 * FROWB;

    int tid = threadIdx.x;
    int wid = tid >> 5, lane = tid & 31;
    int h = blockIdx.y;
    int qb = LT + blockIdx.x * 128;
    const float* Qh = Q + ((size_t)h * LTOT + qb) * HD;
    const float* Kh = Kg + (size_t)h * LTOT * HD;
    const float* Vh = Vg + (size_t)h * LTOT * HD;

    // load Q tile [128][64]
    #pragma unroll
    for (int i = 0; i < 8; i++) {
        int f = tid + i * 256;
        int r = f >> 4, c = (f & 15) * 4;
        *(float4*)&Qs[r * FROW + c] = *(const float4*)(Qh + r * HD + c);
    }

    uint32_t aoff = (uint32_t)((wid * 16 + (lane & 15)) * FROWB + ((lane >> 4) & 1) * 16);
    uint32_t boff = (uint32_t)(((lane & 7) + ((lane >> 4) & 1) * 8) * FROWB
                               + ((lane & 8) ? 16 : 0));

    float m0 = -1e30f, m1 = -1e30f, ls0 = 0.f, ls1 = 0.f;
    float oacc[8][4];
    #pragma unroll
    for (int nt = 0; nt < 8; nt++)
        #pragma unroll
        for (int e = 0; e < 4; e++) oacc[nt][e] = 0.f;

    int prow0 = wid * 16 + (lane >> 2);
    int pcol  = 2 * (lane & 3);

    for (int kb = 0; kb < LTOT; kb += 64) {
        __syncthreads();
        // load K [k][d] and V transposed [d][k]
        #pragma unroll
        for (int i = 0; i < 4; i++) {
            int f = tid + i * 256;
            int r = f >> 4, c = (f & 15) * 4;
            *(float4*)&Ks[r * FROW + c] = *(const float4*)(Kh + (size_t)(kb + r) * HD + c);
            float4 vv = *(const float4*)(Vh + (size_t)(kb + r) * HD + c);
            Vt[(c + 0) * FROW + r] = vv.x;
            Vt[(c + 1) * FROW + r] = vv.y;
            Vt[(c + 2) * FROW + r] = vv.z;
            Vt[(c + 3) * FROW + r] = vv.w;
        }
        __syncthreads();

        // S = Q @ K^T  (per warp: 16 x 64)
        float sacc[8][4];
        #pragma unroll
        for (int nt = 0; nt < 8; nt++)
            #pragma unroll
            for (int e = 0; e < 4; e++) sacc[nt][e] = 0.f;
        #pragma unroll
        for (int ks = 0; ks < 8; ks++) {
            uint32_t af[4], bf[4][4];
            LDSM_X4(af, uQ + aoff + ks * 32);
            #pragma unroll
            for (int p = 0; p < 4; p++)
                LDSM_X4(bf[p], uK + boff + p * 16 * FROWB + ks * 32);
            #pragma unroll
            for (int nt = 0; nt < 8; nt++)
                MMA_TF32(sacc[nt], af, bf[nt >> 1][(nt & 1) ? 2 : 0],
                         bf[nt >> 1][(nt & 1) ? 3 : 1]);
        }

        // online softmax (rows prow0, prow0+8)
        float mx0 = -1e30f, mx1 = -1e30f;
        #pragma unroll
        for (int nt = 0; nt < 8; nt++) {
            mx0 = fmaxf(mx0, fmaxf(sacc[nt][0], sacc[nt][1]));
            mx1 = fmaxf(mx1, fmaxf(sacc[nt][2], sacc[nt][3]));
        }
        mx0 = fmaxf(mx0, __shfl_xor_sync(0xffffffffu, mx0, 1));
        mx0 = fmaxf(mx0, __shfl_xor_sync(0xffffffffu, mx0, 2));
        mx1 = fmaxf(mx1, __shfl_xor_sync(0xffffffffu, mx1, 1));
        mx1 = fmaxf(mx1, __shfl_xor_sync(0xffffffffu, mx1, 2));
        float mn0 = fmaxf(m0, mx0), mn1 = fmaxf(m1, mx1);
        float c0 = __expf(m0 - mn0), c1 = __expf(m1 - mn1);
        float ps0 = 0.f, ps1 = 0.f;
        #pragma unroll
        for (int nt = 0; nt < 8; nt++) {
            float p00 = __expf(sacc[nt][0] - mn0);
            float p01 = __expf(sacc[nt][1] - mn0);
            float p10 = __expf(sacc[nt][2] - mn1);
            float p11 = __expf(sacc[nt][3] - mn1);
            ps0 += p00 + p01; ps1 += p10 + p11;
            int col = nt * 8 + pcol;
            *(float2*)&Ps[prow0 * FROW + col] = make_float2(p00, p01);
            *(float2*)&Ps[(prow0 + 8) * FROW + col] = make_float2(p10, p11);
        }
        ps0 += __shfl_xor_sync(0xffffffffu, ps0, 1);
        ps0 += __shfl_xor_sync(0xffffffffu, ps0, 2);
        ps1 += __shfl_xor_sync(0xffffffffu, ps1, 1);
        ps1 += __shfl_xor_sync(0xffffffffu, ps1, 2);
        ls0 = ls0 * c0 + ps0;
        ls1 = ls1 * c1 + ps1;
        m0 = mn0; m1 = mn1;
        #pragma unroll
        for (int nt = 0; nt < 8; nt++) {
            oacc[nt][0] *= c0; oacc[nt][1] *= c0;
            oacc[nt][2] *= c1; oacc[nt][3] *= c1;
        }
        __syncthreads();

        // O += P @ V   (A = Ps rows of this warp, B = Vt)
        #pragma unroll
        for (int ks = 0; ks < 8; ks++) {
            uint32_t af[4], bf[4][4];
            LDSM_X4(af, uP + aoff + ks * 32);
            #pragma unroll
            for (int p = 0; p < 4; p++)
                LDSM_X4(bf[p], uV + boff + p * 16 * FROWB + ks * 32);
            #pragma unroll
            for (int e = 0; e < 4; e++) CVT_TF32(af[e]);
            #pragma unroll
            for (int nt = 0; nt < 8; nt++)
                MMA_TF32(oacc[nt], af, bf[nt >> 1][(nt & 1) ? 2 : 0],
                         bf[nt >> 1][(nt & 1) ? 3 : 1]);
        }
    }

    float inv0 = 1.f / ls0, inv1 = 1.f / ls1;
    int r0 = qb + prow0, r1 = r0 + 8;
    #pragma unroll
    for (int nt = 0; nt < 8; nt++) {
        int col = h * HD + nt * 8 + pcol;
        *(float2*)&O[(size_t)r0 * HID + col] =
            make_float2(rnd_tf32(oacc[nt][0] * inv0), rnd_tf32(oacc[nt][1] * inv0));
        *(float2*)&O[(size_t)r1 * HID + col] =
            make_float2(rnd_tf32(oacc[nt][2] * inv1), rnd_tf32(oacc[nt][3] * inv1));
    }
}

// ---------------- launch ---------------------------------------------------
extern "C" void kernel_launch(void* const* d_in, const int* in_sizes, int n_in,
                              void* d_out, int out_size)
{
    const float* img   = (const float*)d_in[0];
    const float* txt   = (const float*)d_in[1];
    const float* pe    = (const float*)d_in[2];
    const float* vec   = (const float*)d_in[3];
    const float* imw   = (const float*)d_in[4];
    const float* imb   = (const float*)d_in[5];
    const float* tmw   = (const float*)d_in[6];
    const float* tmb   = (const float*)d_in[7];
    const float* iqkvw = (const float*)d_in[8];
    const float* iqkvb = (const float*)d_in[9];
    const float* iqs   = (const float*)d_in[10];
    const float* iks   = (const float*)d_in[11];
    const float* projw = (const float*)d_in[12];
    const float* projb = (const float*)d_in[13];
    const float* tqkvw = (const float*)d_in[14];
    const float* tqkvb = (const float*)d_in[15];
    const float* tqs   = (const float*)d_in[16];
    const float* tks   = (const float*)d_in[17];
    const float* w1    = (const float*)d_in[18];
    const float* b1    = (const float*)d_in[19];
    const float* w2    = (const float*)d_in[20];
    const float* b2    = (const float*)d_in[21];

    float *mod, *imgm, *txtm, *qi, *qt, *q, *k, *v, *attn, *img2, *ln2, *mlp;
    float *wt_iqkv, *wt_tqkv, *wt_proj, *wt_w1, *wt_w2;
    cudaGetSymbolAddress((void**)&mod,  g_mod);
    cudaGetSymbolAddress((void**)&imgm, g_imgm);
    cudaGetSymbolAddress((void**)&txtm, g_txtm);
    cudaGetSymbolAddress((void**)&qi,   g_qkv_img);
    cudaGetSymbolAddress((void**)&qt,   g_qkv_txt);
    cudaGetSymbolAddress((void**)&q,    g_q);
    cudaGetSymbolAddress((void**)&k,    g_k);
    cudaGetSymbolAddress((void**)&v,    g_v);
    cudaGetSymbolAddress((void**)&attn, g_attn);
    cudaGetSymbolAddress((void**)&img2, g_img2);
    cudaGetSymbolAddress((void**)&ln2,  g_ln2);
    cudaGetSymbolAddress((void**)&mlp,  g_mlp);
    cudaGetSymbolAddress((void**)&wt_iqkv, g_wt_iqkv);
    cudaGetSymbolAddress((void**)&wt_tqkv, g_wt_tqkv);
    cudaGetSymbolAddress((void**)&wt_proj, g_wt_proj);
    cudaGetSymbolAddress((void**)&wt_w1,   g_wt_w1);
    cudaGetSymbolAddress((void**)&wt_w2,   g_wt_w2);

    cudaFuncSetAttribute(flash_tf32, cudaFuncAttributeMaxDynamicSharedMemorySize, FL_SMEM);
    cudaFuncSetAttribute(mma_gemm<0>, cudaFuncAttributeMaxDynamicSharedMemorySize, MM_SMEM);
    cudaFuncSetAttribute(mma_gemm<1>, cudaFuncAttributeMaxDynamicSharedMemorySize, MM_SMEM);
    cudaFuncSetAttribute(mma_gemm<2>, cudaFuncAttributeMaxDynamicSharedMemorySize, MM_SMEM);

    // 0) weight transposes + tf32 rounding ([K,N] -> [N,K])
    { dim3 b(32, 8);
      transpose_k<<<dim3(96, 32),  b>>>(iqkvw, wt_iqkv, HID, 3 * HID);
      transpose_k<<<dim3(96, 32),  b>>>(tqkvw, wt_tqkv, HID, 3 * HID);
      transpose_k<<<dim3(32, 32),  b>>>(projw, wt_proj, HID, HID);
      transpose_k<<<dim3(128, 32), b>>>(w1,    wt_w1,   HID, MLPD);
      transpose_k<<<dim3(32, 128), b>>>(w2,    wt_w2,   MLPD, HID); }
    // 1) modulation vectors
    mod_kernel<<<96, 128>>>(vec, imw, imb, tmw, tmb, mod);
    // 2) LN + modulate (img, txt)
    ln_mod_kernel<<<LI, 256>>>(img, mod, 0, 1024, imgm);
    ln_mod_kernel<<<LT, 256>>>(txt, mod, 6144, 7168, txtm);
    // 3) QKV GEMMs (tf32 mma)
    { dim3 g(24, 16); mma_gemm<0><<<g, 256, MM_SMEM>>>(imgm, wt_iqkv, iqkvb, nullptr, nullptr, qi, 3 * HID, HID); }
    { dim3 g(24, 2);  mma_gemm<0><<<g, 256, MM_SMEM>>>(txtm, wt_tqkv, tqkvb, nullptr, nullptr, qt, 3 * HID, HID); }
    // 4) rms-norm + rope + head layout (tf32-rounded)
    build_qkv_kernel<<<LTOT, 256>>>(qi, qt, iqs, iks, tqs, tks, pe, q, k, v);
    // 5) attention (tf32 flash, img queries only, BQ=128)
    { dim3 g(LI / 128, NHEAD);
      flash_tf32<<<g, 256, FL_SMEM>>>(q, k, v, attn); }
    // 6) proj + gated residual (img rows only)
    { dim3 g(8, 16); mma_gemm<2><<<g, 256, MM_SMEM>>>(attn + (size_t)LT * HID, wt_proj, projb,
                                                      img, mod + 2048, img2, HID, HID); }
    // 7) LN2 + modulate
    ln_mod_kernel<<<LI, 256>>>(img2, mod, 3072, 4096, ln2);
    // 8) MLP (tf32 mma)
    { dim3 g(32, 16); mma_gemm<1><<<g, 256, MM_SMEM>>>(ln2, wt_w1, b1, nullptr, nullptr, mlp, MLPD, HID); }
    { dim3 g(8, 16);  mma_gemm<2><<<g, 256, MM_SMEM>>>(mlp, wt_w2, b2, img2, mod + 5120,
                                                       (float*)d_out, HID, MLPD); }
}

// round 6
// speedup vs baseline: 5.6038x; 1.5071x over previous
#include <cuda_runtime.h>
#include <cuda_fp16.h>
#include <cstdint>
#include <math.h>

// Problem constants
#define HID   1024
#define LT    256
#define LI    2048
#define LTOT  2304
#define NHEAD 16
#define HD    64
#define MLPD  4096

// ---------------- scratch (device globals; no cudaMalloc allowed) ----------
__device__ float  g_mod[12288];
__device__ __half g_imgm[LI * HID];
__device__ __half g_txtm[LT * HID];
__device__ __half g_qkv_img[LI * 3 * HID];
__device__ __half g_qkv_txt[LT * 3 * HID];
__device__ __half g_q[NHEAD * LTOT * HD];
__device__ __half g_k[NHEAD * LTOT * HD];
__device__ __half g_v[NHEAD * LTOT * HD];
__device__ __half g_attn[LTOT * HID];
__device__ float  g_img2[LI * HID];
__device__ __half g_ln2[LI * HID];
__device__ __half g_mlp[LI * MLPD];
// transposed weights [N,K] (fp16)
__device__ __half g_wt_iqkv[3 * HID * HID];
__device__ __half g_wt_tqkv[3 * HID * HID];
__device__ __half g_wt_proj[HID * HID];
__device__ __half g_wt_w1[MLPD * HID];
__device__ __half g_wt_w2[HID * MLPD];

// ---------------- PTX helpers ----------------------------------------------
__device__ __forceinline__ uint32_t smem_u32(const void* p) {
    uint32_t a;
    asm("{ .reg .u64 t; cvta.to.shared.u64 t, %1; cvt.u32.u64 %0, t; }" : "=r"(a) : "l"(p));
    return a;
}
#define CP_ASYNC16(dst, src) \
    asm volatile("cp.async.cg.shared.global [%0], [%1], 16;" :: "r"(dst), "l"(src))
#define CP_COMMIT() asm volatile("cp.async.commit_group;")
#define CP_WAIT(n)  asm volatile("cp.async.wait_group %0;" :: "n"(n))

#define LDSM_X4(r, a)                                                          \
    asm volatile("ldmatrix.sync.aligned.m8n8.x4.shared.b16 {%0,%1,%2,%3}, [%4];" \
        : "=r"((r)[0]), "=r"((r)[1]), "=r"((r)[2]), "=r"((r)[3]) : "r"(a))

// D += A(f16) * B(f16), fp32 accumulate, m16n8k16
#define MMA_F16(d, a, b0, b1)                                                  \
    asm volatile("mma.sync.aligned.m16n8k16.row.col.f32.f16.f16.f32 "          \
        "{%0,%1,%2,%3}, {%4,%5,%6,%7}, {%8,%9}, {%0,%1,%2,%3};"                \
        : "+f"((d)[0]), "+f"((d)[1]), "+f"((d)[2]), "+f"((d)[3])               \
        : "r"((a)[0]), "r"((a)[1]), "r"((a)[2]), "r"((a)[3]),                  \
          "r"(b0), "r"(b1))

// ---------------- weight transpose + f16: W[K,N] -> WT[N,K] ----------------
__global__ void transpose_k(const float* __restrict__ W, __half* __restrict__ WT,
                            int K, int N)
{
    __shared__ float t[32][33];
    int n0 = blockIdx.x * 32, k0 = blockIdx.y * 32;
    int tx = threadIdx.x, ty = threadIdx.y;
    #pragma unroll
    for (int i = 0; i < 32; i += 8)
        t[ty + i][tx] = W[(size_t)(k0 + ty + i) * N + n0 + tx];
    __syncthreads();
    #pragma unroll
    for (int i = 0; i < 32; i += 8)
        WT[(size_t)(n0 + ty + i) * K + k0 + tx] = __float2half_rn(t[tx][ty + i]);
}

// ---------------- modulation: silu(vec) @ mod_w + mod_b --------------------
__global__ void mod_kernel(const float* __restrict__ vec,
                           const float* __restrict__ imw, const float* __restrict__ imb,
                           const float* __restrict__ tmw, const float* __restrict__ tmb,
                           float* __restrict__ mod)
{
    __shared__ float sv[HID];
    int tid = threadIdx.x;
    for (int i = tid; i < HID; i += 128) {
        float x = vec[i];
        sv[i] = x / (1.f + expf(-x));
    }
    __syncthreads();
    int blk = blockIdx.x;
    bool is_img = blk < 48;
    int col = (is_img ? blk : blk - 48) * 128 + tid;
    const float* w = is_img ? imw : tmw;
    const float* b = is_img ? imb : tmb;
    float* out = mod + (is_img ? 0 : 6144);
    float a0 = 0.f, a1 = 0.f, a2 = 0.f, a3 = 0.f;
    for (int d = 0; d < HID; d += 4) {
        a0 += sv[d + 0] * w[(d + 0) * 6144 + col];
        a1 += sv[d + 1] * w[(d + 1) * 6144 + col];
        a2 += sv[d + 2] * w[(d + 2) * 6144 + col];
        a3 += sv[d + 3] * w[(d + 3) * 6144 + col];
    }
    out[col] = b[col] + ((a0 + a1) + (a2 + a3));
}

// ---------------- fused LayerNorm + modulate (fp16 output) -----------------
__global__ void ln_mod_kernel(const float* __restrict__ x,
                              const float* __restrict__ mod,
                              int shift_off, int scale_off,
                              __half* __restrict__ out)
{
    __shared__ float red[2][8];
    int row = blockIdx.x, tid = threadIdx.x;
    float4 xv = ((const float4*)(x + row * HID))[tid];
    float s  = xv.x + xv.y + xv.z + xv.w;
    float s2 = xv.x * xv.x + xv.y * xv.y + xv.z * xv.z + xv.w * xv.w;
    #pragma unroll
    for (int o = 16; o; o >>= 1) {
        s  += __shfl_xor_sync(0xffffffffu, s,  o);
        s2 += __shfl_xor_sync(0xffffffffu, s2, o);
    }
    int warp = tid >> 5, lane = tid & 31;
    if (lane == 0) { red[0][warp] = s; red[1][warp] = s2; }
    __syncthreads();
    s = 0.f; s2 = 0.f;
    #pragma unroll
    for (int w = 0; w < 8; w++) { s += red[0][w]; s2 += red[1][w]; }
    float mean = s * (1.f / HID);
    float var  = s2 * (1.f / HID) - mean * mean;
    float rs = rsqrtf(var + 1e-6f);
    int c = tid * 4;
    float4 sc = *(const float4*)(mod + scale_off + c);
    float4 sh = *(const float4*)(mod + shift_off + c);
    __half2 h01 = __floats2half2_rn((xv.x - mean) * rs * (1.f + sc.x) + sh.x,
                                    (xv.y - mean) * rs * (1.f + sc.y) + sh.y);
    __half2 h23 = __floats2half2_rn((xv.z - mean) * rs * (1.f + sc.z) + sh.z,
                                    (xv.w - mean) * rs * (1.f + sc.w) + sh.w);
    *(__half2*)(out + (size_t)row * HID + c)     = h01;
    *(__half2*)(out + (size_t)row * HID + c + 2) = h23;
}

// ---------------- fp16 mma GEMM: C[M,N] = A[M,K] @ BT[N,K]^T ---------------
// CTA 128x128, BK=64, double-buffered cp.async, padded half rows (144 B).
// 8 warps: warp_m = wid&3 (32 rows), warp_n = wid>>2 (64 cols).
// EPI: 0 = +bias (half out); 1 = gelu(+bias) (half out); 2 = res+gate (float out)
__device__ __forceinline__ float gelu_tanh(float x)
{
    return 0.5f * x * (1.f + tanhf(0.7978845608028654f * (x + 0.044715f * x * x * x)));
}

#define ROWH 144                       // bytes per padded smem row (64 halves + 16B)
#define TILEH (128 * ROWH)             // 18432 B per tile
#define MM_SMEM (4 * TILEH)            // A0 A1 B0 B1 = 73728 B

__device__ __forceinline__ void mm_load_tile(uint32_t sbase, const __half* __restrict__ g,
                                             int K, int k0)
{
    int tid = threadIdx.x;
    #pragma unroll
    for (int i = 0; i < 4; i++) {
        int id = tid + i * 256;
        int r = id >> 3, c = id & 7;               // 8 x 16B chunks per 128B row
        uint32_t dst = sbase + r * ROWH + c * 16;
        const __half* src = g + (size_t)r * K + k0 + c * 8;
        CP_ASYNC16(dst, src);
    }
}

template <int EPI, typename OT>
__global__ void __launch_bounds__(256) mma_gemm(
    const __half* __restrict__ A, const __half* __restrict__ BT,
    const float* __restrict__ bias, const float* __restrict__ res,
    const float* __restrict__ gate, OT* __restrict__ C,
    int N, int K)
{
    extern __shared__ char smem[];
    uint32_t su = smem_u32(smem);
    uint32_t sA[2] = { su,              su + TILEH };
    uint32_t sB[2] = { su + 2 * TILEH,  su + 3 * TILEH };

    int tid = threadIdx.x;
    int wid = tid >> 5, lane = tid & 31;
    int warp_m = wid & 3, warp_n = wid >> 2;
    int row0 = blockIdx.y * 128;
    int col0 = blockIdx.x * 128;
    const __half* Ab = A + (size_t)row0 * K;
    const __half* Bb = BT + (size_t)col0 * K;

    float acc[2][8][4];
    #pragma unroll
    for (int mt = 0; mt < 2; mt++)
        #pragma unroll
        for (int nt = 0; nt < 8; nt++)
            #pragma unroll
            for (int e = 0; e < 4; e++) acc[mt][nt][e] = 0.f;

    // ldmatrix lane offsets: row = base + (lane&15), k-half select = (lane>>4)*16B
    uint32_t aoff = (uint32_t)((warp_m * 32 + (lane & 15)) * ROWH + ((lane >> 4) & 1) * 16);
    uint32_t boff = (uint32_t)((warp_n * 64 + (lane & 15)) * ROWH + ((lane >> 4) & 1) * 16);

    int T = K >> 6;
    mm_load_tile(sA[0], Ab, K, 0);
    mm_load_tile(sB[0], Bb, K, 0);
    CP_COMMIT();

    for (int t = 0; t < T; t++) {
        int b = t & 1;
        if (t + 1 < T) {
            mm_load_tile(sA[b ^ 1], Ab, K, (t + 1) * 64);
            mm_load_tile(sB[b ^ 1], Bb, K, (t + 1) * 64);
            CP_COMMIT();
            CP_WAIT(1);
        } else {
            CP_WAIT(0);
        }
        __syncthreads();

        uint32_t Abase = sA[b] + aoff;
        uint32_t Bbase = sB[b] + boff;
        #pragma unroll
        for (int ks = 0; ks < 4; ks++) {           // k16 steps within BK=64
            uint32_t af[2][4], bf[4][4];
            LDSM_X4(af[0], Abase + ks * 32);
            LDSM_X4(af[1], Abase + 16 * ROWH + ks * 32);
            #pragma unroll
            for (int p = 0; p < 4; p++)
                LDSM_X4(bf[p], Bbase + p * 16 * ROWH + ks * 32);
            #pragma unroll
            for (int mt = 0; mt < 2; mt++)
                #pragma unroll
                for (int nt = 0; nt < 8; nt++) {
                    int p = nt >> 1, q = nt & 1;
                    MMA_F16(acc[mt][nt], af[mt], bf[p][q], bf[p][q + 2]);
                }
        }
        __syncthreads();
    }

    int qr = lane >> 2, qc = (lane & 3) * 2;
    #pragma unroll
    for (int mt = 0; mt < 2; mt++) {
        int gr0 = row0 + warp_m * 32 + mt * 16 + qr;
        #pragma unroll
        for (int nt = 0; nt < 8; nt++) {
            int gc = col0 + warp_n * 64 + nt * 8 + qc;
            float2 bv = *(const float2*)(bias + gc);
            #pragma unroll
            for (int h = 0; h < 2; h++) {
                int gr = gr0 + h * 8;
                float vx = acc[mt][nt][2 * h + 0] + bv.x;
                float vy = acc[mt][nt][2 * h + 1] + bv.y;
                if (EPI == 0) {
                    *(__half2*)((__half*)C + (size_t)gr * N + gc) =
                        __floats2half2_rn(vx, vy);
                } else if (EPI == 1) {
                    *(__half2*)((__half*)C + (size_t)gr * N + gc) =
                        __floats2half2_rn(gelu_tanh(vx), gelu_tanh(vy));
                } else {
                    float2 rr = *(const float2*)(res + (size_t)gr * N + gc);
                    float2 gg = *(const float2*)(gate + gc);
                    float2 v = make_float2(rr.x + gg.x * vx, rr.y + gg.y * vy);
                    *(float2*)((float*)C + (size_t)gr * N + gc) = v;
                }
            }
        }
    }
}

// ---------------- build q/k/v: rms-norm + rope + head layout (fp16) --------
__global__ void build_qkv_kernel(const __half* __restrict__ qkv_img,
                                 const __half* __restrict__ qkv_txt,
                                 const float* __restrict__ iqs, const float* __restrict__ iks,
                                 const float* __restrict__ tqs, const float* __restrict__ tks,
                                 const float* __restrict__ pe,
                                 __half* __restrict__ q, __half* __restrict__ k,
                                 __half* __restrict__ v)
{
    int s = blockIdx.x;
    int warp = threadIdx.x >> 5, lane = threadIdx.x & 31;
    bool is_txt = s < LT;
    const __half* src = is_txt ? (qkv_txt + (size_t)s * 3072)
                               : (qkv_img + (size_t)(s - LT) * 3072);
    for (int u = warp; u < 48; u += 8) {
        int which = u >> 4;       // 0=q 1=k 2=v
        int h = u & 15;
        const __half* base = src + which * HID + h * HD;
        float x0 = __half2float(base[2 * lane]);
        float x1 = __half2float(base[2 * lane + 1]);
        size_t didx = ((size_t)h * LTOT + s) * HD + 2 * lane;
        if (which == 2) {
            v[didx]     = __float2half_rn(x0);
            v[didx + 1] = __float2half_rn(x1);
        } else {
            float ss = x0 * x0 + x1 * x1;
            #pragma unroll
            for (int o = 16; o; o >>= 1) ss += __shfl_xor_sync(0xffffffffu, ss, o);
            float r = rsqrtf(ss * (1.f / HD) + 1e-6f);
            const float* sc = (which == 0) ? (is_txt ? tqs : iqs)
                                           : (is_txt ? tks : iks);
            x0 *= r * sc[2 * lane];
            x1 *= r * sc[2 * lane + 1];
            const float* p = pe + (size_t)s * 128 + lane * 4;
            float o0 = p[0] * x0 + p[1] * x1;
            float o1 = p[2] * x0 + p[3] * x1;
            if (which == 0) { o0 *= 0.125f; o1 *= 0.125f; }  // fold 1/sqrt(HD)
            __half* dst = (which == 0) ? q : k;
            dst[didx]     = __float2half_rn(o0);
            dst[didx + 1] = __float2half_rn(o1);
        }
    }
}

// ---------------- fp16 flash attention: BQ=128, BK=64, HD=64 ---------------
// 8 warps / 256 threads. Only img query rows (qb >= LT).
#define FROWH 72                 // halves per padded smem row (64 + 8)
#define FROWB 144                // bytes per padded smem row
#define FL_SMEM ((128 + 64 + 64 + 128) * FROWB)   // Q, K, Vt, P = 55296 B

__global__ void __launch_bounds__(256) flash_f16(
    const __half* __restrict__ Q, const __half* __restrict__ Kg,
    const __half* __restrict__ Vg, __half* __restrict__ O)
{
    extern __shared__ __half hsm[];
    __half* Qs = hsm;                        // [q][d] 128 rows
    __half* Ks = hsm + 128 * FROWH;          // [k][d] 64 rows
    __half* Vt = hsm + 192 * FROWH;          // [d][k] 64 rows
    __half* Ps = hsm + 256 * FROWH;          // [q][k] 128 rows
    uint32_t su = smem_u32(hsm);
    uint32_t uQ = su, uK = su + 128 * FROWB, uV = su + 192 * FROWB, uP = su + 256 * FROWB;

    int tid = threadIdx.x;
    int wid = tid >> 5, lane = tid & 31;
    int h = blockIdx.y;
    int qb = LT + blockIdx.x * 128;
    const __half* Qh = Q + ((size_t)h * LTOT + qb) * HD;
    const __half* Kh = Kg + (size_t)h * LTOT * HD;
    const __half* Vh = Vg + (size_t)h * LTOT * HD;

    // load Q tile [128][64] halves (rows = 128 B = 8 x 16B chunks)
    #pragma unroll
    for (int i = 0; i < 4; i++) {
        int f = tid + i * 256;
        int r = f >> 3, c = (f & 7) * 8;
        *(float4*)&Qs[r * FROWH + c] = *(const float4*)(Qh + (size_t)r * HD + c);
    }

    uint32_t aoff = (uint32_t)((wid * 16 + (lane & 15)) * FROWB + ((lane >> 4) & 1) * 16);
    uint32_t boff = (uint32_t)((lane & 15) * FROWB + ((lane >> 4) & 1) * 16);

    float m0 = -1e30f, m1 = -1e30f, ls0 = 0.f, ls1 = 0.f;
    float oacc[8][4];
    #pragma unroll
    for (int nt = 0; nt < 8; nt++)
        #pragma unroll
        for (int e = 0; e < 4; e++) oacc[nt][e] = 0.f;

    int prow0 = wid * 16 + (lane >> 2);
    int pcol  = 2 * (lane & 3);

    for (int kb = 0; kb < LTOT; kb += 64) {
        __syncthreads();
        // load K [k][d] and V transposed [d][k]
        #pragma unroll
        for (int i = 0; i < 2; i++) {
            int f = tid + i * 256;
            int r = f >> 3, c = (f & 7) * 8;
            *(float4*)&Ks[r * FROWH + c] = *(const float4*)(Kh + (size_t)(kb + r) * HD + c);
            float4 vv = *(const float4*)(Vh + (size_t)(kb + r) * HD + c);
            const __half* vh = (const __half*)&vv;
            #pragma unroll
            for (int j = 0; j < 8; j++)
                Vt[(c + j) * FROWH + r] = vh[j];
        }
        __syncthreads();

        // S = Q @ K^T  (per warp: 16 x 64)
        float sacc[8][4];
        #pragma unroll
        for (int nt = 0; nt < 8; nt++)
            #pragma unroll
            for (int e = 0; e < 4; e++) sacc[nt][e] = 0.f;
        #pragma unroll
        for (int ks = 0; ks < 4; ks++) {
            uint32_t af[4], bf[4][4];
            LDSM_X4(af, uQ + aoff + ks * 32);
            #pragma unroll
            for (int p = 0; p < 4; p++)
                LDSM_X4(bf[p], uK + boff + p * 16 * FROWB + ks * 32);
            #pragma unroll
            for (int nt = 0; nt < 8; nt++) {
                int p = nt >> 1, q = nt & 1;
                MMA_F16(sacc[nt], af, bf[p][q], bf[p][q + 2]);
            }
        }

        // online softmax (rows prow0, prow0+8)
        float mx0 = -1e30f, mx1 = -1e30f;
        #pragma unroll
        for (int nt = 0; nt < 8; nt++) {
            mx0 = fmaxf(mx0, fmaxf(sacc[nt][0], sacc[nt][1]));
            mx1 = fmaxf(mx1, fmaxf(sacc[nt][2], sacc[nt][3]));
        }
        mx0 = fmaxf(mx0, __shfl_xor_sync(0xffffffffu, mx0, 1));
        mx0 = fmaxf(mx0, __shfl_xor_sync(0xffffffffu, mx0, 2));
        mx1 = fmaxf(mx1, __shfl_xor_sync(0xffffffffu, mx1, 1));
        mx1 = fmaxf(mx1, __shfl_xor_sync(0xffffffffu, mx1, 2));
        float mn0 = fmaxf(m0, mx0), mn1 = fmaxf(m1, mx1);
        float c0 = __expf(m0 - mn0), c1 = __expf(m1 - mn1);
        float ps0 = 0.f, ps1 = 0.f;
        #pragma unroll
        for (int nt = 0; nt < 8; nt++) {
            float p00 = __expf(sacc[nt][0] - mn0);
            float p01 = __expf(sacc[nt][1] - mn0);
            float p10 = __expf(sacc[nt][2] - mn1);
            float p11 = __expf(sacc[nt][3] - mn1);
            ps0 += p00 + p01; ps1 += p10 + p11;
            int col = nt * 8 + pcol;
            *(__half2*)&Ps[prow0 * FROWH + col] = __floats2half2_rn(p00, p01);
            *(__half2*)&Ps[(prow0 + 8) * FROWH + col] = __floats2half2_rn(p10, p11);
        }
        ps0 += __shfl_xor_sync(0xffffffffu, ps0, 1);
        ps0 += __shfl_xor_sync(0xffffffffu, ps0, 2);
        ps1 += __shfl_xor_sync(0xffffffffu, ps1, 1);
        ps1 += __shfl_xor_sync(0xffffffffu, ps1, 2);
        ls0 = ls0 * c0 + ps0;
        ls1 = ls1 * c1 + ps1;
        m0 = mn0; m1 = mn1;
        #pragma unroll
        for (int nt = 0; nt < 8; nt++) {
            oacc[nt][0] *= c0; oacc[nt][1] *= c0;
            oacc[nt][2] *= c1; oacc[nt][3] *= c1;
        }
        __syncwarp();

        // O += P @ V   (A = Ps rows of this warp, B = Vt)
        #pragma unroll
        for (int ks = 0; ks < 4; ks++) {
            uint32_t af[4], bf[4][4];
            LDSM_X4(af, uP + aoff + ks * 32);
            #pragma unroll
            for (int p = 0; p < 4; p++)
                LDSM_X4(bf[p], uV + boff + p * 16 * FROWB + ks * 32);
            #pragma unroll
            for (int nt = 0; nt < 8; nt++) {
                int p = nt >> 1, q = nt & 1;
                MMA_F16(oacc[nt], af, bf[p][q], bf[p][q + 2]);
            }
        }
    }

    float inv0 = 1.f / ls0, inv1 = 1.f / ls1;
    int r0 = qb + prow0, r1 = r0 + 8;
    #pragma unroll
    for (int nt = 0; nt < 8; nt++) {
        int col = h * HD + nt * 8 + pcol;
        *(__half2*)(O + (size_t)r0 * HID + col) =
            __floats2half2_rn(oacc[nt][0] * inv0, oacc[nt][1] * inv0);
        *(__half2*)(O + (size_t)r1 * HID + col) =
            __floats2half2_rn(oacc[nt][2] * inv1, oacc[nt][3] * inv1);
    }
}

// ---------------- launch ---------------------------------------------------
extern "C" void kernel_launch(void* const* d_in, const int* in_sizes, int n_in,
                              void* d_out, int out_size)
{
    const float* img   = (const float*)d_in[0];
    const float* txt   = (const float*)d_in[1];
    const float* pe    = (const float*)d_in[2];
    const float* vec   = (const float*)d_in[3];
    const float* imw   = (const float*)d_in[4];
    const float* imb   = (const float*)d_in[5];
    const float* tmw   = (const float*)d_in[6];
    const float* tmb   = (const float*)d_in[7];
    const float* iqkvw = (const float*)d_in[8];
    const float* iqkvb = (const float*)d_in[9];
    const float* iqs   = (const float*)d_in[10];
    const float* iks   = (const float*)d_in[11];
    const float* projw = (const float*)d_in[12];
    const float* projb = (const float*)d_in[13];
    const float* tqkvw = (const float*)d_in[14];
    const float* tqkvb = (const float*)d_in[15];
    const float* tqs   = (const float*)d_in[16];
    const float* tks   = (const float*)d_in[17];
    const float* w1    = (const float*)d_in[18];
    const float* b1    = (const float*)d_in[19];
    const float* w2    = (const float*)d_in[20];
    const float* b2    = (const float*)d_in[21];

    float *mod, *img2;
    __half *imgm, *txtm, *qi, *qt, *q, *k, *v, *attn, *ln2, *mlp;
    __half *wt_iqkv, *wt_tqkv, *wt_proj, *wt_w1, *wt_w2;
    cudaGetSymbolAddress((void**)&mod,  g_mod);
    cudaGetSymbolAddress((void**)&imgm, g_imgm);
    cudaGetSymbolAddress((void**)&txtm, g_txtm);
    cudaGetSymbolAddress((void**)&qi,   g_qkv_img);
    cudaGetSymbolAddress((void**)&qt,   g_qkv_txt);
    cudaGetSymbolAddress((void**)&q,    g_q);
    cudaGetSymbolAddress((void**)&k,    g_k);
    cudaGetSymbolAddress((void**)&v,    g_v);
    cudaGetSymbolAddress((void**)&attn, g_attn);
    cudaGetSymbolAddress((void**)&img2, g_img2);
    cudaGetSymbolAddress((void**)&ln2,  g_ln2);
    cudaGetSymbolAddress((void**)&mlp,  g_mlp);
    cudaGetSymbolAddress((void**)&wt_iqkv, g_wt_iqkv);
    cudaGetSymbolAddress((void**)&wt_tqkv, g_wt_tqkv);
    cudaGetSymbolAddress((void**)&wt_proj, g_wt_proj);
    cudaGetSymbolAddress((void**)&wt_w1,   g_wt_w1);
    cudaGetSymbolAddress((void**)&wt_w2,   g_wt_w2);

    cudaFuncSetAttribute(flash_f16, cudaFuncAttributeMaxDynamicSharedMemorySize, FL_SMEM);
    cudaFuncSetAttribute(mma_gemm<0, __half>, cudaFuncAttributeMaxDynamicSharedMemorySize, MM_SMEM);
    cudaFuncSetAttribute(mma_gemm<1, __half>, cudaFuncAttributeMaxDynamicSharedMemorySize, MM_SMEM);
    cudaFuncSetAttribute(mma_gemm<2, float>,  cudaFuncAttributeMaxDynamicSharedMemorySize, MM_SMEM);

    // 0) weight transposes -> fp16 [N,K]
    { dim3 b(32, 8);
      transpose_k<<<dim3(96, 32),  b>>>(iqkvw, wt_iqkv, HID, 3 * HID);
      transpose_k<<<dim3(96, 32),  b>>>(tqkvw, wt_tqkv, HID, 3 * HID);
      transpose_k<<<dim3(32, 32),  b>>>(projw, wt_proj, HID, HID);
      transpose_k<<<dim3(128, 32), b>>>(w1,    wt_w1,   HID, MLPD);
      transpose_k<<<dim3(32, 128), b>>>(w2,    wt_w2,   MLPD, HID); }
    // 1) modulation vectors
    mod_kernel<<<96, 128>>>(vec, imw, imb, tmw, tmb, mod);
    // 2) LN + modulate (img, txt) -> fp16
    ln_mod_kernel<<<LI, 256>>>(img, mod, 0, 1024, imgm);
    ln_mod_kernel<<<LT, 256>>>(txt, mod, 6144, 7168, txtm);
    // 3) QKV GEMMs (fp16 mma)
    { dim3 g(24, 16); mma_gemm<0, __half><<<g, 256, MM_SMEM>>>(imgm, wt_iqkv, iqkvb, nullptr, nullptr, qi, 3 * HID, HID); }
    { dim3 g(24, 2);  mma_gemm<0, __half><<<g, 256, MM_SMEM>>>(txtm, wt_tqkv, tqkvb, nullptr, nullptr, qt, 3 * HID, HID); }
    // 4) rms-norm + rope + head layout (fp16)
    build_qkv_kernel<<<LTOT, 256>>>(qi, qt, iqs, iks, tqs, tks, pe, q, k, v);
    // 5) attention (fp16 flash, img queries only, BQ=128)
    { dim3 g(LI / 128, NHEAD);
      flash_f16<<<g, 256, FL_SMEM>>>(q, k, v, attn); }
    // 6) proj + gated residual (img rows only) -> fp32
    { dim3 g(8, 16); mma_gemm<2, float><<<g, 256, MM_SMEM>>>(attn + (size_t)LT * HID, wt_proj, projb,
                                                             img, mod + 2048, img2, HID, HID); }
    // 7) LN2 + modulate -> fp16
    ln_mod_kernel<<<LI, 256>>>(img2, mod, 3072, 4096, ln2);
    // 8) MLP (fp16 mma)
    { dim3 g(32, 16); mma_gemm<1, __half><<<g, 256, MM_SMEM>>>(ln2, wt_w1, b1, nullptr, nullptr, mlp, MLPD, HID); }
    { dim3 g(8, 16);  mma_gemm<2, float><<<g, 256, MM_SMEM>>>(mlp, wt_w2, b2, img2, mod + 5120,
                                                              (float*)d_out, HID, MLPD); }
}